// round 2
// baseline (speedup 1.0000x reference)
#include <cuda_runtime.h>

// WindowAttentionGlobal: per-window fused
//   kv = x @ W_kv + b_kv          -> k,v [H][N][hd]
//   attn = softmax(q*scale @ k^T + bias)
//   o = attn @ v ; out = o @ W_proj + b_proj
//
// Shapes: B_=4096 windows, N=49 tokens, DIM=128, HEADS=4, hd=32.
// One CTA per window, 256 threads.

#define NWIN   49
#define DIMC   128
#define HEADS  4
#define HD     32
#define SCALE  0.17677669529663689f   // 32^-0.5

// smem layout (floats):
//   xs/os : 49*132 = 6468   (x tile, later reused as attention output, pitch 132 to dodge bank conflicts)
//   ks    : 4*49*32 = 6272  [h][m][d]
//   vs    : 4*49*32 = 6272
//   ps    : 4*49*49 = 9604  softmax probs [h][n][m]
#define OFF_XS 0
#define OFF_KS 6468
#define OFF_VS 12740
#define OFF_PS 19012
#define SMEM_FLOATS (OFF_PS + HEADS*NWIN*NWIN)   // 28616
#define SMEM_BYTES  (SMEM_FLOATS * 4)            // 114464

__global__ __launch_bounds__(256, 2)
void winattn_kernel(const float* __restrict__ x,
                    const float* __restrict__ q_global,
                    const float* __restrict__ tbl,       // [169,4]
                    const float* __restrict__ W_kv,      // [128,256]
                    const float* __restrict__ b_kv,      // [256]
                    const float* __restrict__ W_proj,    // [128,128]
                    const float* __restrict__ b_proj,    // [128]
                    const int*   __restrict__ rel_index, // [49,49]
                    float* __restrict__ out)             // [4096,49,128]
{
    extern __shared__ float smem[];
    float* xs = smem + OFF_XS;   // phase 1-2: x tile (row pitch 128). phase 3b-4: o (row pitch 132)
    float* ks = smem + OFF_KS;
    float* vs = smem + OFF_VS;
    float* ps = smem + OFF_PS;

    const int b = blockIdx.x;
    const int t = threadIdx.x;

    // ---------------- phase 1: load x tile [49][128], contiguous ----------------
    {
        const float4* src = (const float4*)(x + (size_t)b * (NWIN * DIMC));
        float4* dst = (float4*)xs;
        #pragma unroll 2
        for (int i = t; i < NWIN * DIMC / 4; i += 256) dst[i] = src[i];
    }
    __syncthreads();

    // ---------------- phase 2: kv GEMM — thread t owns output column t ----------
    // kv[n, t], t = which*128 + h*32 + d  (which: 0=k, 1=v)
    {
        float acc[NWIN];
        const float bk = __ldg(&b_kv[t]);
        #pragma unroll
        for (int n = 0; n < NWIN; n++) acc[n] = bk;

        #pragma unroll 4
        for (int d0 = 0; d0 < DIMC; d0 += 4) {
            const float w0 = __ldg(&W_kv[(d0 + 0) * 256 + t]);
            const float w1 = __ldg(&W_kv[(d0 + 1) * 256 + t]);
            const float w2 = __ldg(&W_kv[(d0 + 2) * 256 + t]);
            const float w3 = __ldg(&W_kv[(d0 + 3) * 256 + t]);
            const float4* xv4 = (const float4*)xs + (d0 >> 2);
            #pragma unroll
            for (int n = 0; n < NWIN; n++) {
                float4 xv = xv4[n * 32];           // broadcast LDS.128
                acc[n] = fmaf(xv.x, w0, acc[n]);
                acc[n] = fmaf(xv.y, w1, acc[n]);
                acc[n] = fmaf(xv.z, w2, acc[n]);
                acc[n] = fmaf(xv.w, w3, acc[n]);
            }
        }
        float* dst = (t < 128) ? ks : vs;
        const int h = (t & 127) >> 5;
        const int d = t & 31;
        #pragma unroll
        for (int n = 0; n < NWIN; n++) dst[h * (NWIN * HD) + n * HD + d] = acc[n];
    }
    __syncthreads();

    // ---------------- phase 3a: scores + softmax, one (h,n) row per thread ------
    if (t < HEADS * NWIN) {
        const int h = t / NWIN;
        const int n = t % NWIN;

        float4 q[8];
        const float4* qg = (const float4*)(q_global
                            + ((size_t)(b >> 6) * HEADS + h) * (NWIN * HD) + n * HD);
        #pragma unroll
        for (int j = 0; j < 8; j++) {
            q[j] = __ldg(&qg[j]);
            q[j].x *= SCALE; q[j].y *= SCALE; q[j].z *= SCALE; q[j].w *= SCALE;
        }

        float s[NWIN];
        float mx = -1e30f;
        const int* ridx = rel_index + n * NWIN;
        #pragma unroll 7
        for (int m = 0; m < NWIN; m++) {
            const float4* kk = (const float4*)(ks + h * (NWIN * HD) + m * HD);
            float dot = 0.f;
            #pragma unroll
            for (int j = 0; j < 8; j++) {
                float4 kv = kk[j];
                dot = fmaf(q[j].x, kv.x, dot);
                dot = fmaf(q[j].y, kv.y, dot);
                dot = fmaf(q[j].z, kv.z, dot);
                dot = fmaf(q[j].w, kv.w, dot);
            }
            dot += __ldg(&tbl[__ldg(&ridx[m]) * HEADS + h]);
            s[m] = dot;
            mx = fmaxf(mx, dot);
        }
        float sum = 0.f;
        #pragma unroll
        for (int m = 0; m < NWIN; m++) { s[m] = __expf(s[m] - mx); sum += s[m]; }
        const float inv = 1.f / sum;
        float* prow = ps + (h * NWIN + n) * NWIN;
        #pragma unroll
        for (int m = 0; m < NWIN; m++) prow[m] = s[m] * inv;   // stride-49 across threads: conflict-free
    }
    __syncthreads();

    // ---------------- phase 3b: o[h][n][:] = p-row @ v, one (h,n) row per thread
    if (t < HEADS * NWIN) {
        const int h = t / NWIN;
        const int n = t % NWIN;
        float4 o[8];
        #pragma unroll
        for (int j = 0; j < 8; j++) o[j] = make_float4(0.f, 0.f, 0.f, 0.f);

        const float* prow = ps + (h * NWIN + n) * NWIN;
        #pragma unroll 7
        for (int m = 0; m < NWIN; m++) {
            const float p = prow[m];
            const float4* vv = (const float4*)(vs + h * (NWIN * HD) + m * HD);  // broadcast
            #pragma unroll
            for (int j = 0; j < 8; j++) {
                float4 v4 = vv[j];
                o[j].x = fmaf(p, v4.x, o[j].x);
                o[j].y = fmaf(p, v4.y, o[j].y);
                o[j].z = fmaf(p, v4.z, o[j].z);
                o[j].w = fmaf(p, v4.w, o[j].w);
            }
        }
        // write to os (= xs region, pitch 132 floats so STS.128 across n is conflict-free)
        float4* orow = (float4*)(xs + n * 132 + h * HD);
        #pragma unroll
        for (int j = 0; j < 8; j++) orow[j] = o[j];
    }
    __syncthreads();

    // ---------------- phase 4: proj GEMM — out[n][c] = o[n][:] @ W_proj[:,c] + b
    {
        const int c  = t & 127;
        const int n0 = (t < 128) ? 0 : 25;
        const int nr = (t < 128) ? 25 : 24;
        float acc[25];
        const float bp = __ldg(&b_proj[c]);
        #pragma unroll
        for (int i = 0; i < 25; i++) acc[i] = bp;

        #pragma unroll 4
        for (int d0 = 0; d0 < DIMC; d0 += 4) {
            const float w0 = __ldg(&W_proj[(d0 + 0) * DIMC + c]);
            const float w1 = __ldg(&W_proj[(d0 + 1) * DIMC + c]);
            const float w2 = __ldg(&W_proj[(d0 + 2) * DIMC + c]);
            const float w3 = __ldg(&W_proj[(d0 + 3) * DIMC + c]);
            #pragma unroll
            for (int i = 0; i < 25; i++) {
                if (i < nr) {
                    float4 xv = *(const float4*)(xs + (n0 + i) * 132 + d0);  // broadcast
                    acc[i] = fmaf(xv.x, w0, acc[i]);
                    acc[i] = fmaf(xv.y, w1, acc[i]);
                    acc[i] = fmaf(xv.z, w2, acc[i]);
                    acc[i] = fmaf(xv.w, w3, acc[i]);
                }
            }
        }
        float* obase = out + (size_t)b * (NWIN * DIMC) + c;
        #pragma unroll
        for (int i = 0; i < 25; i++) {
            if (i < nr) obase[(n0 + i) * DIMC] = acc[i];   // coalesced across c
        }
    }
}

extern "C" void kernel_launch(void* const* d_in, const int* in_sizes, int n_in,
                              void* d_out, int out_size)
{
    const float* x         = (const float*)d_in[0];
    const float* q_global  = (const float*)d_in[1];
    const float* tbl       = (const float*)d_in[2];
    const float* W_kv      = (const float*)d_in[3];
    const float* b_kv      = (const float*)d_in[4];
    const float* W_proj    = (const float*)d_in[5];
    const float* b_proj    = (const float*)d_in[6];
    const int*   rel_index = (const int*)d_in[7];
    float* out = (float*)d_out;

    cudaFuncSetAttribute(winattn_kernel,
                         cudaFuncAttributeMaxDynamicSharedMemorySize, SMEM_BYTES);

    winattn_kernel<<<4096, 256, SMEM_BYTES>>>(
        x, q_global, tbl, W_kv, b_kv, W_proj, b_proj, rel_index, out);
}

// round 6
// speedup vs baseline: 1.1981x; 1.1981x over previous
#include <cuda_runtime.h>
#include <cuda_fp16.h>
#include <cstdint>

// ============================================================
// WindowAttentionGlobal — 3-stage pipeline (HMMA mma.sync path;
// tcgen05 unavailable: harness PTX targets compute_103 base)
//   1) gemm_kv   : kv = X @ W_kv + b_kv        (m16n8k16 f16 MMA, fp32 accum)
//   2) winattn   : per-window softmax attention (fp32 FFMA)
//   3) gemm_proj : out = o @ W_proj + b_proj   (m16n8k16 f16 MMA, fp32 accum)
// ============================================================

#define NWIN   49
#define DIMC   128
#define HEADS  4
#define HD     32
#define SCALE  0.17677669529663689f
#define NTOK   200704            // 4096 windows * 49 tokens
#define MTILE  128
#define NTILES (NTOK / MTILE)    // 1568, exact

// scratch (device-global: the sanctioned no-alloc path)
__device__ __half g_kv[(size_t)NTOK * 256];   // ~103 MB
__device__ __half g_o [(size_t)NTOK * 128];   // ~51 MB

// single dynamic-smem symbol for the whole TU
extern __shared__ char dynsmem[];

#define LDT 136                  // smem row pitch in halves (16B-aligned rows)

__device__ __forceinline__ uint32_t h2u(__half2 h) {
    return *reinterpret_cast<uint32_t*>(&h);
}

__device__ __forceinline__ void mma16816(float* d, const uint32_t* a, const uint32_t* b) {
    asm volatile(
        "mma.sync.aligned.m16n8k16.row.col.f32.f16.f16.f32 "
        "{%0,%1,%2,%3}, {%4,%5,%6,%7}, {%8,%9}, {%0,%1,%2,%3};"
        : "+f"(d[0]), "+f"(d[1]), "+f"(d[2]), "+f"(d[3])
        : "r"(a[0]), "r"(a[1]), "r"(a[2]), "r"(a[3]), "r"(b[0]), "r"(b[1]));
}

// ============================================================
// Kernel 1: kv = X @ W_kv + b_kv
//   grid (1568, 2): blockIdx.y picks the 128-col half of the 256-col output.
//   CTA tile M=128,N=128,K=128; 8 warps as 4(M) x 2(N), warp tile 32x64.
// ============================================================
#define GE_SMEM (2 * 128 * LDT * 2)   // A + B halves = 69632 B

__global__ __launch_bounds__(256)
void gemm_kv(const float* __restrict__ x, const float* __restrict__ W,
             const float* __restrict__ bias)
{
    __half* As = (__half*)dynsmem;            // [128][LDT]
    __half* Bs = As + 128 * LDT;              // [128][LDT]  (BT: [n][k])
    const int t = threadIdx.x;
    const int ny = blockIdx.y;

    // A: x[128 rows][128 k] fp32 -> fp16
    const float* xrow = x + (size_t)blockIdx.x * MTILE * DIMC;
    #pragma unroll
    for (int i = t; i < 2048; i += 256) {
        int row = i >> 4, k8 = (i & 15) * 8;
        const float4* s = (const float4*)(xrow + row * DIMC + k8);
        float4 a = s[0], b = s[1];
        *(uint4*)&As[row * LDT + k8] = make_uint4(
            h2u(__floats2half2_rn(a.x, a.y)), h2u(__floats2half2_rn(a.z, a.w)),
            h2u(__floats2half2_rn(b.x, b.y)), h2u(__floats2half2_rn(b.z, b.w)));
    }
    // B: BT[n][k] = W_kv[k][ny*128 + n] fp32 -> fp16
    #pragma unroll
    for (int i = t; i < 2048; i += 256) {
        int n = i & 127, k0 = (i >> 7) * 8;
        int gcol = ny * 128 + n;
        float f[8];
        #pragma unroll
        for (int j = 0; j < 8; j++) f[j] = __ldg(&W[(k0 + j) * 256 + gcol]);
        *(uint4*)&Bs[n * LDT + k0] = make_uint4(
            h2u(__floats2half2_rn(f[0], f[1])), h2u(__floats2half2_rn(f[2], f[3])),
            h2u(__floats2half2_rn(f[4], f[5])), h2u(__floats2half2_rn(f[6], f[7])));
    }
    __syncthreads();

    const int wid = t >> 5, l = t & 31;
    const int wm = (wid >> 1) * 32, wn = (wid & 1) * 64;
    float acc[2][8][4];
    #pragma unroll
    for (int i = 0; i < 2; i++)
        #pragma unroll
        for (int j = 0; j < 8; j++)
            acc[i][j][0] = acc[i][j][1] = acc[i][j][2] = acc[i][j][3] = 0.f;

    #pragma unroll
    for (int k0 = 0; k0 < 128; k0 += 16) {
        const int ac = k0 + (l & 3) * 2;
        uint32_t afr[2][4], bfr[8][2];
        #pragma unroll
        for (int i = 0; i < 2; i++) {
            int ar = wm + i * 16 + (l >> 2);
            afr[i][0] = *(const uint32_t*)&As[ar * LDT + ac];
            afr[i][1] = *(const uint32_t*)&As[(ar + 8) * LDT + ac];
            afr[i][2] = *(const uint32_t*)&As[ar * LDT + ac + 8];
            afr[i][3] = *(const uint32_t*)&As[(ar + 8) * LDT + ac + 8];
        }
        #pragma unroll
        for (int j = 0; j < 8; j++) {
            int br = wn + j * 8 + (l >> 2);
            bfr[j][0] = *(const uint32_t*)&Bs[br * LDT + ac];
            bfr[j][1] = *(const uint32_t*)&Bs[br * LDT + ac + 8];
        }
        #pragma unroll
        for (int i = 0; i < 2; i++)
            #pragma unroll
            for (int j = 0; j < 8; j++)
                mma16816(acc[i][j], afr[i], bfr[j]);
    }

    // epilogue: +bias, fp16, -> g_kv[row][256]
    const size_t rbase = (size_t)blockIdx.x * MTILE + wm + (l >> 2);
    #pragma unroll
    for (int i = 0; i < 2; i++) {
        #pragma unroll
        for (int j = 0; j < 8; j++) {
            int gcol = ny * 128 + wn + j * 8 + (l & 3) * 2;
            float b0 = __ldg(&bias[gcol]), b1 = __ldg(&bias[gcol + 1]);
            __half2* p0 = (__half2*)&g_kv[(rbase + i * 16) * 256 + gcol];
            __half2* p1 = (__half2*)&g_kv[(rbase + i * 16 + 8) * 256 + gcol];
            *p0 = __floats2half2_rn(acc[i][j][0] + b0, acc[i][j][1] + b1);
            *p1 = __floats2half2_rn(acc[i][j][2] + b0, acc[i][j][3] + b1);
        }
    }
}

// ============================================================
// Kernel 2: per-window attention (fp32), kv fp16 in / o fp16 out
// ============================================================
#define AT_KS 0
#define AT_VS 6272
#define AT_PS 12544
#define AT_SMEM ((12544 + 9604) * 4)   // 88592 B

__global__ __launch_bounds__(256, 2)
void winattn(const float* __restrict__ q_global,
             const float* __restrict__ tbl,
             const int* __restrict__ rel_index)
{
    float* smf = (float*)dynsmem;
    float* ks = smf + AT_KS;
    float* vs = smf + AT_VS;
    float* ps = smf + AT_PS;
    const int b = blockIdx.x, t = threadIdx.x;

    // load kv tile: [49][256] fp16 -> ks/vs fp32 [h][n][d]
    {
        const __half2* src = (const __half2*)(g_kv + (size_t)b * NWIN * 256);
        #pragma unroll 2
        for (int i = t; i < NWIN * 128; i += 256) {
            int n = i >> 7, p = i & 127, c = 2 * p;
            float2 f = __half22float2(src[i]);
            float* dst = (c < 128) ? ks : vs;
            int cc = c & 127, h = cc >> 5, d = cc & 31;
            *(float2*)(dst + h * (NWIN * HD) + n * HD + d) = f;
        }
    }
    __syncthreads();

    // scores + softmax
    if (t < HEADS * NWIN) {
        const int h = t / NWIN, n = t % NWIN;
        float4 q[8];
        const float4* qg = (const float4*)(q_global
                            + ((size_t)(b >> 6) * HEADS + h) * (NWIN * HD) + n * HD);
        #pragma unroll
        for (int j = 0; j < 8; j++) {
            q[j] = __ldg(&qg[j]);
            q[j].x *= SCALE; q[j].y *= SCALE; q[j].z *= SCALE; q[j].w *= SCALE;
        }
        float s[NWIN];
        float mx = -1e30f;
        const int* ridx = rel_index + n * NWIN;
        #pragma unroll 7
        for (int m = 0; m < NWIN; m++) {
            const float4* kk = (const float4*)(ks + h * (NWIN * HD) + m * HD);
            float dot = 0.f;
            #pragma unroll
            for (int j = 0; j < 8; j++) {
                float4 kv = kk[j];
                dot = fmaf(q[j].x, kv.x, dot);
                dot = fmaf(q[j].y, kv.y, dot);
                dot = fmaf(q[j].z, kv.z, dot);
                dot = fmaf(q[j].w, kv.w, dot);
            }
            dot += __ldg(&tbl[__ldg(&ridx[m]) * HEADS + h]);
            s[m] = dot;
            mx = fmaxf(mx, dot);
        }
        float sum = 0.f;
        #pragma unroll
        for (int m = 0; m < NWIN; m++) { s[m] = __expf(s[m] - mx); sum += s[m]; }
        const float inv = 1.f / sum;
        float* prow = ps + (h * NWIN + n) * NWIN;
        #pragma unroll
        for (int m = 0; m < NWIN; m++) prow[m] = s[m] * inv;
    }
    __syncthreads();

    // o = P @ V  -> g_o fp16
    if (t < HEADS * NWIN) {
        const int h = t / NWIN, n = t % NWIN;
        float4 o[8];
        #pragma unroll
        for (int j = 0; j < 8; j++) o[j] = make_float4(0.f, 0.f, 0.f, 0.f);
        const float* prow = ps + (h * NWIN + n) * NWIN;
        #pragma unroll 7
        for (int m = 0; m < NWIN; m++) {
            const float p = prow[m];
            const float4* vv = (const float4*)(vs + h * (NWIN * HD) + m * HD);
            #pragma unroll
            for (int j = 0; j < 8; j++) {
                float4 v4 = vv[j];
                o[j].x = fmaf(p, v4.x, o[j].x);
                o[j].y = fmaf(p, v4.y, o[j].y);
                o[j].z = fmaf(p, v4.z, o[j].z);
                o[j].w = fmaf(p, v4.w, o[j].w);
            }
        }
        uint32_t h2v[16];
        #pragma unroll
        for (int j = 0; j < 8; j++) {
            h2v[2 * j]     = h2u(__floats2half2_rn(o[j].x, o[j].y));
            h2v[2 * j + 1] = h2u(__floats2half2_rn(o[j].z, o[j].w));
        }
        uint4* dst = (uint4*)(g_o + ((size_t)b * NWIN + n) * 128 + h * HD);
        dst[0] = make_uint4(h2v[0], h2v[1], h2v[2], h2v[3]);
        dst[1] = make_uint4(h2v[4], h2v[5], h2v[6], h2v[7]);
        dst[2] = make_uint4(h2v[8], h2v[9], h2v[10], h2v[11]);
        dst[3] = make_uint4(h2v[12], h2v[13], h2v[14], h2v[15]);
    }
}

// ============================================================
// Kernel 3: out = o @ W_proj + b_proj   (M=128, N=128, K=128)
// ============================================================
__global__ __launch_bounds__(256)
void gemm_proj(const float* __restrict__ W, const float* __restrict__ bias,
               float* __restrict__ out)
{
    __half* As = (__half*)dynsmem;            // [128][LDT]
    __half* Bs = As + 128 * LDT;
    const int t = threadIdx.x;

    // A: o fp16 direct copy
    const __half* arow = g_o + (size_t)blockIdx.x * MTILE * DIMC;
    #pragma unroll
    for (int i = t; i < 2048; i += 256) {
        int row = i >> 4, k8 = (i & 15) * 8;
        uint4 v = *(const uint4*)(arow + row * DIMC + k8);
        *(uint4*)&As[row * LDT + k8] = v;
    }
    // B: BT[n][k] = W_proj[k][n] fp32 -> fp16
    #pragma unroll
    for (int i = t; i < 2048; i += 256) {
        int n = i & 127, k0 = (i >> 7) * 8;
        float f[8];
        #pragma unroll
        for (int j = 0; j < 8; j++) f[j] = __ldg(&W[(k0 + j) * DIMC + n]);
        *(uint4*)&Bs[n * LDT + k0] = make_uint4(
            h2u(__floats2half2_rn(f[0], f[1])), h2u(__floats2half2_rn(f[2], f[3])),
            h2u(__floats2half2_rn(f[4], f[5])), h2u(__floats2half2_rn(f[6], f[7])));
    }
    __syncthreads();

    const int wid = t >> 5, l = t & 31;
    const int wm = (wid >> 1) * 32, wn = (wid & 1) * 64;
    float acc[2][8][4];
    #pragma unroll
    for (int i = 0; i < 2; i++)
        #pragma unroll
        for (int j = 0; j < 8; j++)
            acc[i][j][0] = acc[i][j][1] = acc[i][j][2] = acc[i][j][3] = 0.f;

    #pragma unroll
    for (int k0 = 0; k0 < 128; k0 += 16) {
        const int ac = k0 + (l & 3) * 2;
        uint32_t afr[2][4], bfr[8][2];
        #pragma unroll
        for (int i = 0; i < 2; i++) {
            int ar = wm + i * 16 + (l >> 2);
            afr[i][0] = *(const uint32_t*)&As[ar * LDT + ac];
            afr[i][1] = *(const uint32_t*)&As[(ar + 8) * LDT + ac];
            afr[i][2] = *(const uint32_t*)&As[ar * LDT + ac + 8];
            afr[i][3] = *(const uint32_t*)&As[(ar + 8) * LDT + ac + 8];
        }
        #pragma unroll
        for (int j = 0; j < 8; j++) {
            int br = wn + j * 8 + (l >> 2);
            bfr[j][0] = *(const uint32_t*)&Bs[br * LDT + ac];
            bfr[j][1] = *(const uint32_t*)&Bs[br * LDT + ac + 8];
        }
        #pragma unroll
        for (int i = 0; i < 2; i++)
            #pragma unroll
            for (int j = 0; j < 8; j++)
                mma16816(acc[i][j], afr[i], bfr[j]);
    }

    // epilogue: +bias -> fp32 out[row][128]
    const size_t rbase = (size_t)blockIdx.x * MTILE + wm + (l >> 2);
    #pragma unroll
    for (int i = 0; i < 2; i++) {
        #pragma unroll
        for (int j = 0; j < 8; j++) {
            int col = wn + j * 8 + (l & 3) * 2;
            float b0 = __ldg(&bias[col]), b1 = __ldg(&bias[col + 1]);
            float2* p0 = (float2*)&out[(rbase + i * 16) * DIMC + col];
            float2* p1 = (float2*)&out[(rbase + i * 16 + 8) * DIMC + col];
            *p0 = make_float2(acc[i][j][0] + b0, acc[i][j][1] + b1);
            *p1 = make_float2(acc[i][j][2] + b0, acc[i][j][3] + b1);
        }
    }
}

// ============================================================
extern "C" void kernel_launch(void* const* d_in, const int* in_sizes, int n_in,
                              void* d_out, int out_size)
{
    const float* x         = (const float*)d_in[0];
    const float* q_global  = (const float*)d_in[1];
    const float* tbl       = (const float*)d_in[2];
    const float* W_kv      = (const float*)d_in[3];
    const float* b_kv      = (const float*)d_in[4];
    const float* W_proj    = (const float*)d_in[5];
    const float* b_proj    = (const float*)d_in[6];
    const int*   rel_index = (const int*)d_in[7];
    float* out = (float*)d_out;

    cudaFuncSetAttribute(gemm_kv,   cudaFuncAttributeMaxDynamicSharedMemorySize, GE_SMEM);
    cudaFuncSetAttribute(winattn,   cudaFuncAttributeMaxDynamicSharedMemorySize, AT_SMEM);
    cudaFuncSetAttribute(gemm_proj, cudaFuncAttributeMaxDynamicSharedMemorySize, GE_SMEM);

    gemm_kv  <<<dim3(NTILES, 2), 256, GE_SMEM>>>(x, W_kv, b_kv);
    winattn  <<<4096, 256, AT_SMEM>>>(q_global, tbl, rel_index);
    gemm_proj<<<NTILES, 256, GE_SMEM>>>(W_proj, b_proj, out);
}

// round 11
// speedup vs baseline: 3.5844x; 2.9917x over previous
#include <cuda_runtime.h>
#include <cuda_fp16.h>
#include <cstdint>

// ============================================================
// WindowAttentionGlobal — all matmuls on HMMA (mma.sync m16n8k16)
//   0) prep      : W_kv/W_proj -> fp16 transposed; bias table [4][49][64]
//   1) gemm_kv   : kv = X @ W_kv + b_kv          (M=64,N=256,K=128 tiles)
//   2) winattn   : QK^T + softmax + PV, fragment-resident
//   3) gemm_proj : out = o @ W_proj + b_proj     (M=64,N=128,K=128 tiles)
// ============================================================

#define NWIN   49
#define DIMC   128
#define HEADS  4
#define SCALE  0.17677669529663689f
#define NTOK   200704
#define NTILES (NTOK / 64)       // 3136

__device__ __half g_kv[(size_t)NTOK * 256];
__device__ __half g_o [(size_t)NTOK * 128];
__device__ __half g_wkvT[256 * 128];     // [n][k]
__device__ __half g_wprojT[128 * 128];   // [n][k]
__device__ float  g_bias[4 * 49 * 64];   // [h][r][c], c>=49 -> -1e9

extern __shared__ char dynsmem[];

__device__ __forceinline__ uint32_t smem_u32(const void* p) {
    uint32_t a;
    asm("{ .reg .u64 t; cvta.to.shared.u64 t, %1; cvt.u32.u64 %0, t; }" : "=r"(a) : "l"(p));
    return a;
}
__device__ __forceinline__ uint32_t h2u(__half2 h) { return *reinterpret_cast<uint32_t*>(&h); }

#define LDSM_X4(r, addr)                                                      \
    asm volatile("ldmatrix.sync.aligned.m8n8.x4.shared.b16 {%0,%1,%2,%3}, [%4];" \
                 : "=r"((r)[0]), "=r"((r)[1]), "=r"((r)[2]), "=r"((r)[3]) : "r"(addr))
#define LDSM_X4_T(r, addr)                                                    \
    asm volatile("ldmatrix.sync.aligned.m8n8.x4.trans.shared.b16 {%0,%1,%2,%3}, [%4];" \
                 : "=r"((r)[0]), "=r"((r)[1]), "=r"((r)[2]), "=r"((r)[3]) : "r"(addr))

__device__ __forceinline__ void mma16816(float* d, const uint32_t* a,
                                         uint32_t b0, uint32_t b1) {
    asm volatile(
        "mma.sync.aligned.m16n8k16.row.col.f32.f16.f16.f32 "
        "{%0,%1,%2,%3}, {%4,%5,%6,%7}, {%8,%9}, {%0,%1,%2,%3};"
        : "+f"(d[0]), "+f"(d[1]), "+f"(d[2]), "+f"(d[3])
        : "r"(a[0]), "r"(a[1]), "r"(a[2]), "r"(a[3]), "r"(b0), "r"(b1));
}

// lane-address helper for ldmatrix x4 (A / B-nontrans / B-trans all share it)
__device__ __forceinline__ uint32_t ldsm_addr(uint32_t base2B, int row0, int pitch,
                                              int col0, int l) {
    int row = row0 + (l & 7) + ((l >> 3) & 1) * 8;
    int col = col0 + (l >> 4) * 8;
    return base2B + (uint32_t)(row * pitch + col) * 2u;
}

// ============================================================
// Kernel 0: prep (weights fp16 transpose + bias table)
// ============================================================
__global__ void prep(const float* __restrict__ Wkv, const float* __restrict__ Wp,
                     const float* __restrict__ tbl, const int* __restrict__ ridx)
{
    int idx = blockIdx.x * 256 + threadIdx.x;
    if (idx < 32768) {                       // wkvT[n][k]
        int n = idx >> 7, k = idx & 127;
        g_wkvT[idx] = __float2half(Wkv[k * 256 + n]);
    } else if (idx < 49152) {                // wprojT[n][k]
        int i = idx - 32768, n = i >> 7, k = i & 127;
        g_wprojT[i] = __float2half(Wp[k * 128 + n]);
    } else if (idx < 49152 + 12544) {        // bias[h][r][c64]
        int i = idx - 49152;
        int h = i / 3136, r = (i % 3136) >> 6, c = i & 63;
        g_bias[i] = (c < 49) ? tbl[ridx[r * 49 + c] * 4 + h] : -1e9f;
    }
}

// ============================================================
// Kernel 1: gemm_kv  (CTA tile M=64, N=256, K=128; 8 warps 2Mx4N)
// ============================================================
#define KV_BS (64 * 136)                  // halves
#define KV_SMEM ((64 * 136 + 256 * 136) * 2)   // 87040 B

__global__ __launch_bounds__(256)
void gemm_kv(const float* __restrict__ x, const float* __restrict__ bkv)
{
    __half* As = (__half*)dynsmem;               // [64][136]
    __half* Bs = As + KV_BS;                     // [256][136]
    const int t = threadIdx.x, l = t & 31, wid = t >> 5;
    const uint32_t sbA = smem_u32(As), sbB = smem_u32(Bs);

    // A: x fp32 [64][128] -> fp16
    const float* xrow = x + (size_t)blockIdx.x * 64 * DIMC;
    #pragma unroll
    for (int p = 0; p < 8; p++) {
        int i = t + p * 256;                      // 2048 float4
        int row = i >> 5, f4 = i & 31;            // 32 float4/row
        float4 v = *(const float4*)(xrow + row * DIMC + f4 * 4);
        *(uint2*)&As[row * 136 + f4 * 4] = make_uint2(
            h2u(__floats2half2_rn(v.x, v.y)), h2u(__floats2half2_rn(v.z, v.w)));
    }
    // B: g_wkvT fp16 [256][128] = 4096 uint4
    #pragma unroll
    for (int p = 0; p < 16; p++) {
        int i = t + p * 256;
        int row = i >> 4, c = i & 15;
        *(uint4*)&Bs[row * 136 + c * 8] = *(const uint4*)&g_wkvT[row * 128 + c * 8];
    }
    __syncthreads();

    const int wm = (wid >> 2) * 32, wn = (wid & 3) * 64;
    float acc[2][8][4];
    #pragma unroll
    for (int i = 0; i < 2; i++)
        #pragma unroll
        for (int j = 0; j < 8; j++)
            acc[i][j][0] = acc[i][j][1] = acc[i][j][2] = acc[i][j][3] = 0.f;

    #pragma unroll
    for (int kk = 0; kk < 128; kk += 16) {
        uint32_t a[2][4], b[4][4];
        #pragma unroll
        for (int i = 0; i < 2; i++) LDSM_X4(a[i], ldsm_addr(sbA, wm + 16 * i, 136, kk, l));
        #pragma unroll
        for (int g = 0; g < 4; g++) LDSM_X4(b[g], ldsm_addr(sbB, wn + 16 * g, 136, kk, l));
        #pragma unroll
        for (int i = 0; i < 2; i++)
            #pragma unroll
            for (int g = 0; g < 4; g++) {
                mma16816(acc[i][2 * g],     a[i], b[g][0], b[g][2]);
                mma16816(acc[i][2 * g + 1], a[i], b[g][1], b[g][3]);
            }
    }
    __syncthreads();

    // stage epilogue in smem (reuse Bs as [64][264] halves)
    __half* os = Bs;
    const int l2 = 2 * (l & 3), l4 = l >> 2;
    #pragma unroll
    for (int i = 0; i < 2; i++) {
        int rA = wm + 16 * i + l4;
        #pragma unroll
        for (int j = 0; j < 8; j++) {
            int c = wn + 8 * j + l2;
            float2 bb = *(const float2*)&bkv[c];
            *(__half2*)&os[rA * 264 + c] =
                __floats2half2_rn(acc[i][j][0] + bb.x, acc[i][j][1] + bb.y);
            *(__half2*)&os[(rA + 8) * 264 + c] =
                __floats2half2_rn(acc[i][j][2] + bb.x, acc[i][j][3] + bb.y);
        }
    }
    __syncthreads();

    // store: 64 rows x 32 uint4 = 2048 uint4
    __half* dst = g_kv + (size_t)blockIdx.x * 64 * 256;
    #pragma unroll
    for (int p = 0; p < 8; p++) {
        int i = t + p * 256;
        int row = i >> 5, c = i & 31;
        *(uint4*)&dst[row * 256 + c * 8] = *(const uint4*)&os[row * 264 + c * 8];
    }
}

// ============================================================
// Kernel 2: winattn — fragment-resident attention
//   smem: kvs [64][264] halves (33792B) + qs [4][64][40] halves (20480B)
// ============================================================
#define AT_QS (64 * 264)                          // halves offset
#define AT_SMEM ((64 * 264 + 4 * 64 * 40) * 2)    // 54272 B

__global__ __launch_bounds__(256, 2)
void winattn(const float* __restrict__ q_global)
{
    __half* kvs = (__half*)dynsmem;               // [64][264]
    __half* qs  = kvs + AT_QS;                    // [4][64][40]
    const int b = blockIdx.x, t = threadIdx.x, l = t & 31, wid = t >> 5;
    const uint32_t sbKV = smem_u32(kvs), sbQ = smem_u32(qs);

    // ---- load kv rows (49 real + 15 zero) ----
    {
        const uint4* src = (const uint4*)(g_kv + (size_t)b * NWIN * 256);
        for (int i = t; i < 1568; i += 256) {     // 49*32
            int row = i >> 5, c = i & 31;
            *(uint4*)&kvs[row * 264 + c * 8] = src[row * 32 + c];
        }
        for (int i = t; i < 480; i += 256) {      // 15*32 zero
            int row = 49 + (i >> 5), c = i & 31;
            *(uint4*)&kvs[row * 264 + c * 8] = make_uint4(0, 0, 0, 0);
        }
    }
    // ---- load q (scaled fp16) + zero pad rows ----
    {
        const float* qg = q_global + (size_t)(b >> 6) * (HEADS * NWIN * 32);
        for (int i = t; i < 1568; i += 256) {     // 4*49*8 float4
            int h = i / 392, rem = i % 392, r = rem >> 3, f = rem & 7;
            float4 v = *(const float4*)(qg + (h * NWIN + r) * 32 + f * 4);
            *(uint2*)&qs[h * 2560 + r * 40 + f * 4] = make_uint2(
                h2u(__floats2half2_rn(v.x * SCALE, v.y * SCALE)),
                h2u(__floats2half2_rn(v.z * SCALE, v.w * SCALE)));
        }
        for (int i = t; i < 600; i += 256) {      // 4*15*10 uint2
            int h = i / 150, rr = (i % 150) / 10, u = i % 10;
            *(uint2*)&qs[h * 2560 + (49 + rr) * 40 + u * 4] = make_uint2(0, 0);
        }
    }
    __syncthreads();

    const int h = wid >> 1, wm = (wid & 1) * 32;
    const int l2 = 2 * (l & 3), l4 = l >> 2;
    const uint32_t qbase = sbQ + (uint32_t)h * 2560u * 2u;

    // ---- QK^T : S[64x64] per head, warp owns 32 rows ----
    float S[2][8][4];
    #pragma unroll
    for (int i = 0; i < 2; i++)
        #pragma unroll
        for (int j = 0; j < 8; j++)
            S[i][j][0] = S[i][j][1] = S[i][j][2] = S[i][j][3] = 0.f;

    #pragma unroll
    for (int kk = 0; kk < 32; kk += 16) {
        uint32_t a[2][4], bk[4][4];
        #pragma unroll
        for (int i = 0; i < 2; i++) LDSM_X4(a[i], ldsm_addr(qbase, wm + 16 * i, 40, kk, l));
        #pragma unroll
        for (int g = 0; g < 4; g++)
            LDSM_X4(bk[g], ldsm_addr(sbKV, 16 * g, 264, h * 32 + kk, l));
        #pragma unroll
        for (int i = 0; i < 2; i++)
            #pragma unroll
            for (int g = 0; g < 4; g++) {
                mma16816(S[i][2 * g],     a[i], bk[g][0], bk[g][2]);
                mma16816(S[i][2 * g + 1], a[i], bk[g][1], bk[g][3]);
            }
    }

    // ---- bias + mask + softmax in fragments ----
    uint32_t ph[2][4][4];                          // P fp16 A-frags per k16 tile
    #pragma unroll
    for (int i = 0; i < 2; i++) {
        int rA = wm + 16 * i + l4, rB = rA + 8;
        const float* bA = &g_bias[(h * 49 + (rA < 49 ? rA : 48)) * 64];
        const float* bB = &g_bias[(h * 49 + (rB < 49 ? rB : 48)) * 64];
        #pragma unroll
        for (int j = 0; j < 8; j++) {
            float2 fA = *(const float2*)&bA[8 * j + l2];
            float2 fB = *(const float2*)&bB[8 * j + l2];
            S[i][j][0] += fA.x; S[i][j][1] += fA.y;
            S[i][j][2] += fB.x; S[i][j][3] += fB.y;
        }
        float mA = -1e30f, mB = -1e30f;
        #pragma unroll
        for (int j = 0; j < 8; j++) {
            mA = fmaxf(mA, fmaxf(S[i][j][0], S[i][j][1]));
            mB = fmaxf(mB, fmaxf(S[i][j][2], S[i][j][3]));
        }
        mA = fmaxf(mA, __shfl_xor_sync(0xffffffffu, mA, 1));
        mA = fmaxf(mA, __shfl_xor_sync(0xffffffffu, mA, 2));
        mB = fmaxf(mB, __shfl_xor_sync(0xffffffffu, mB, 1));
        mB = fmaxf(mB, __shfl_xor_sync(0xffffffffu, mB, 2));
        float sA = 0.f, sB = 0.f;
        #pragma unroll
        for (int j = 0; j < 8; j++) {
            S[i][j][0] = __expf(S[i][j][0] - mA); sA += S[i][j][0];
            S[i][j][1] = __expf(S[i][j][1] - mA); sA += S[i][j][1];
            S[i][j][2] = __expf(S[i][j][2] - mB); sB += S[i][j][2];
            S[i][j][3] = __expf(S[i][j][3] - mB); sB += S[i][j][3];
        }
        sA += __shfl_xor_sync(0xffffffffu, sA, 1);
        sA += __shfl_xor_sync(0xffffffffu, sA, 2);
        sB += __shfl_xor_sync(0xffffffffu, sB, 1);
        sB += __shfl_xor_sync(0xffffffffu, sB, 2);
        float iA = 1.f / sA, iB = 1.f / sB;
        #pragma unroll
        for (int tp = 0; tp < 4; tp++) {
            ph[i][tp][0] = h2u(__floats2half2_rn(S[i][2 * tp][0] * iA, S[i][2 * tp][1] * iA));
            ph[i][tp][1] = h2u(__floats2half2_rn(S[i][2 * tp][2] * iB, S[i][2 * tp][3] * iB));
            ph[i][tp][2] = h2u(__floats2half2_rn(S[i][2 * tp + 1][0] * iA, S[i][2 * tp + 1][1] * iA));
            ph[i][tp][3] = h2u(__floats2half2_rn(S[i][2 * tp + 1][2] * iB, S[i][2 * tp + 1][3] * iB));
        }
    }

    // ---- PV : O[64x32] per head ----
    float O[2][4][4];
    #pragma unroll
    for (int i = 0; i < 2; i++)
        #pragma unroll
        for (int j = 0; j < 4; j++)
            O[i][j][0] = O[i][j][1] = O[i][j][2] = O[i][j][3] = 0.f;

    #pragma unroll
    for (int tp = 0; tp < 4; tp++) {
        uint32_t bv[2][4];
        #pragma unroll
        for (int g = 0; g < 2; g++)
            LDSM_X4_T(bv[g], ldsm_addr(sbKV, 16 * tp, 264, 128 + h * 32 + 16 * g, l));
        #pragma unroll
        for (int i = 0; i < 2; i++)
            #pragma unroll
            for (int jd = 0; jd < 4; jd++) {
                int g = jd >> 1;
                if ((jd & 1) == 0) mma16816(O[i][jd], ph[i][tp], bv[g][0], bv[g][1]);
                else               mma16816(O[i][jd], ph[i][tp], bv[g][2], bv[g][3]);
            }
    }

    // ---- stage o in smem (reuse qs as [64][136]) then coalesced store ----
    __syncthreads();
    __half* os = qs;
    #pragma unroll
    for (int i = 0; i < 2; i++) {
        int rA = wm + 16 * i + l4;
        #pragma unroll
        for (int jd = 0; jd < 4; jd++) {
            int c = h * 32 + 8 * jd + l2;
            *(__half2*)&os[rA * 136 + c]       = __floats2half2_rn(O[i][jd][0], O[i][jd][1]);
            *(__half2*)&os[(rA + 8) * 136 + c] = __floats2half2_rn(O[i][jd][2], O[i][jd][3]);
        }
    }
    __syncthreads();
    {
        uint4* dst = (uint4*)(g_o + (size_t)b * NWIN * 128);
        for (int i = t; i < 784; i += 256) {      // 49*16
            int row = i >> 4, c = i & 15;
            dst[row * 16 + c] = *(const uint4*)&os[row * 136 + c * 8];
        }
    }
}

// ============================================================
// Kernel 3: gemm_proj  (CTA tile M=64, N=128, K=128; warps 2Mx4N)
// ============================================================
#define PJ_SMEM ((64 * 136 + 128 * 136) * 2)      // 52224 B

__global__ __launch_bounds__(256)
void gemm_proj(const float* __restrict__ bp, float* __restrict__ out)
{
    __half* As = (__half*)dynsmem;                // [64][136]
    __half* Bs = As + 64 * 136;                   // [128][136]
    const int t = threadIdx.x, l = t & 31, wid = t >> 5;
    const uint32_t sbA = smem_u32(As), sbB = smem_u32(Bs);

    const __half* arow = g_o + (size_t)blockIdx.x * 64 * DIMC;
    #pragma unroll
    for (int p = 0; p < 4; p++) {
        int i = t + p * 256;                      // 1024 uint4
        int row = i >> 4, c = i & 15;
        *(uint4*)&As[row * 136 + c * 8] = *(const uint4*)&arow[row * 128 + c * 8];
    }
    #pragma unroll
    for (int p = 0; p < 8; p++) {
        int i = t + p * 256;                      // 2048 uint4
        int row = i >> 4, c = i & 15;
        *(uint4*)&Bs[row * 136 + c * 8] = *(const uint4*)&g_wprojT[row * 128 + c * 8];
    }
    __syncthreads();

    const int wm = (wid >> 2) * 32, wn = (wid & 3) * 32;
    float acc[2][4][4];
    #pragma unroll
    for (int i = 0; i < 2; i++)
        #pragma unroll
        for (int j = 0; j < 4; j++)
            acc[i][j][0] = acc[i][j][1] = acc[i][j][2] = acc[i][j][3] = 0.f;

    #pragma unroll
    for (int kk = 0; kk < 128; kk += 16) {
        uint32_t a[2][4], b[2][4];
        #pragma unroll
        for (int i = 0; i < 2; i++) LDSM_X4(a[i], ldsm_addr(sbA, wm + 16 * i, 136, kk, l));
        #pragma unroll
        for (int g = 0; g < 2; g++) LDSM_X4(b[g], ldsm_addr(sbB, wn + 16 * g, 136, kk, l));
        #pragma unroll
        for (int i = 0; i < 2; i++)
            #pragma unroll
            for (int g = 0; g < 2; g++) {
                mma16816(acc[i][2 * g],     a[i], b[g][0], b[g][2]);
                mma16816(acc[i][2 * g + 1], a[i], b[g][1], b[g][3]);
            }
    }
    __syncthreads();

    // stage fp32 epilogue in smem [64][132] floats (reuse As/Bs area)
    float* os = (float*)dynsmem;
    const int l2 = 2 * (l & 3), l4 = l >> 2;
    #pragma unroll
    for (int i = 0; i < 2; i++) {
        int rA = wm + 16 * i + l4;
        #pragma unroll
        for (int j = 0; j < 4; j++) {
            int c = wn + 8 * j + l2;
            float2 bb = *(const float2*)&bp[c];
            *(float2*)&os[rA * 132 + c]       = make_float2(acc[i][j][0] + bb.x, acc[i][j][1] + bb.y);
            *(float2*)&os[(rA + 8) * 132 + c] = make_float2(acc[i][j][2] + bb.x, acc[i][j][3] + bb.y);
        }
    }
    __syncthreads();
    float* dst = out + (size_t)blockIdx.x * 64 * DIMC;
    #pragma unroll
    for (int p = 0; p < 8; p++) {
        int i = t + p * 256;                      // 2048 float4
        int row = i >> 5, c4 = i & 31;
        *(float4*)&dst[row * 128 + c4 * 4] = *(const float4*)&os[row * 132 + c4 * 4];
    }
}

// ============================================================
extern "C" void kernel_launch(void* const* d_in, const int* in_sizes, int n_in,
                              void* d_out, int out_size)
{
    const float* x         = (const float*)d_in[0];
    const float* q_global  = (const float*)d_in[1];
    const float* tbl       = (const float*)d_in[2];
    const float* W_kv      = (const float*)d_in[3];
    const float* b_kv      = (const float*)d_in[4];
    const float* W_proj    = (const float*)d_in[5];
    const float* b_proj    = (const float*)d_in[6];
    const int*   rel_index = (const int*)d_in[7];
    float* out = (float*)d_out;

    cudaFuncSetAttribute(gemm_kv,   cudaFuncAttributeMaxDynamicSharedMemorySize, KV_SMEM);
    cudaFuncSetAttribute(winattn,   cudaFuncAttributeMaxDynamicSharedMemorySize, AT_SMEM);
    cudaFuncSetAttribute(gemm_proj, cudaFuncAttributeMaxDynamicSharedMemorySize, PJ_SMEM);

    prep<<<242, 256>>>(W_kv, W_proj, tbl, rel_index);
    gemm_kv  <<<NTILES, 256, KV_SMEM>>>(x, b_kv);
    winattn  <<<4096,  256, AT_SMEM>>>(q_global);
    gemm_proj<<<NTILES, 256, PJ_SMEM>>>(b_proj, out);
}

// round 13
// speedup vs baseline: 4.0155x; 1.1203x over previous
#include <cuda_runtime.h>
#include <cuda_fp16.h>
#include <cstdint>

// ============================================================
// WindowAttentionGlobal — FULLY FUSED, one CTA per window.
//   prep  : W_kv/W_proj -> fp16 transposed; bias table [4][49][64]
//   fused : x->fp16 -> kv GEMM (2 passes) -> attention -> proj -> out
// All intermediates live in smem; DRAM = x in + out only.
// ============================================================

#define NWIN   49
#define DIMC   128
#define HEADS  4
#define SCALE  0.17677669529663689f

__device__ __half g_wkvT[256 * 128];     // [n][k]
__device__ __half g_wprojT[128 * 128];   // [n][k]
__device__ float  g_bias[4 * 49 * 64];   // [h][r][c], c>=49 -> -1e9

extern __shared__ char dynsmem[];

// smem layout in halves:
//   As  [64][136]  @0        17408 B   (x tile, later o tile)
//   Bs  [128][136] @8704     34816 B   (weight chunk)
//   kvs [64][264]  @26112    33792 B   (kv tile; later fp32 out [64][132])
//   qs  [4][64][40]@43008    20480 B
#define F_AS 0
#define F_BS 8704
#define F_KV 26112
#define F_QS 43008
#define FU_SMEM (53248 * 2)   // 106496 B

__device__ __forceinline__ uint32_t smem_u32(const void* p) {
    uint32_t a;
    asm("{ .reg .u64 t; cvta.to.shared.u64 t, %1; cvt.u32.u64 %0, t; }" : "=r"(a) : "l"(p));
    return a;
}
__device__ __forceinline__ uint32_t h2u(__half2 h) { return *reinterpret_cast<uint32_t*>(&h); }

#define LDSM_X4(r, addr)                                                      \
    asm volatile("ldmatrix.sync.aligned.m8n8.x4.shared.b16 {%0,%1,%2,%3}, [%4];" \
                 : "=r"((r)[0]), "=r"((r)[1]), "=r"((r)[2]), "=r"((r)[3]) : "r"(addr))
#define LDSM_X4_T(r, addr)                                                    \
    asm volatile("ldmatrix.sync.aligned.m8n8.x4.trans.shared.b16 {%0,%1,%2,%3}, [%4];" \
                 : "=r"((r)[0]), "=r"((r)[1]), "=r"((r)[2]), "=r"((r)[3]) : "r"(addr))

__device__ __forceinline__ void mma16816(float* d, const uint32_t* a,
                                         uint32_t b0, uint32_t b1) {
    asm volatile(
        "mma.sync.aligned.m16n8k16.row.col.f32.f16.f16.f32 "
        "{%0,%1,%2,%3}, {%4,%5,%6,%7}, {%8,%9}, {%0,%1,%2,%3};"
        : "+f"(d[0]), "+f"(d[1]), "+f"(d[2]), "+f"(d[3])
        : "r"(a[0]), "r"(a[1]), "r"(a[2]), "r"(a[3]), "r"(b0), "r"(b1));
}

__device__ __forceinline__ uint32_t ldsm_addr(uint32_t base2B, int row0, int pitch,
                                              int col0, int l) {
    int row = row0 + (l & 7) + ((l >> 3) & 1) * 8;
    int col = col0 + (l >> 4) * 8;
    return base2B + (uint32_t)(row * pitch + col) * 2u;
}

// 64x128x128 warp-tiled MMA: A[64][136], B[128][136], 8 warps 2Mx4N, warp 32x32
__device__ __forceinline__ void gemm64x128(uint32_t sbA, uint32_t sbB, int wm, int wn,
                                           int l, float acc[2][4][4]) {
    #pragma unroll
    for (int kk = 0; kk < 128; kk += 16) {
        uint32_t a[2][4], b[2][4];
        #pragma unroll
        for (int i = 0; i < 2; i++) LDSM_X4(a[i], ldsm_addr(sbA, wm + 16 * i, 136, kk, l));
        #pragma unroll
        for (int g = 0; g < 2; g++) LDSM_X4(b[g], ldsm_addr(sbB, wn + 16 * g, 136, kk, l));
        #pragma unroll
        for (int i = 0; i < 2; i++)
            #pragma unroll
            for (int g = 0; g < 2; g++) {
                mma16816(acc[i][2 * g],     a[i], b[g][0], b[g][2]);
                mma16816(acc[i][2 * g + 1], a[i], b[g][1], b[g][3]);
            }
    }
}

// ============================================================
// prep: weights fp16 transpose + bias table
// ============================================================
__global__ void prep(const float* __restrict__ Wkv, const float* __restrict__ Wp,
                     const float* __restrict__ tbl, const int* __restrict__ ridx)
{
    int idx = blockIdx.x * 256 + threadIdx.x;
    if (idx < 32768) {
        int n = idx >> 7, k = idx & 127;
        g_wkvT[idx] = __float2half(Wkv[k * 256 + n]);
    } else if (idx < 49152) {
        int i = idx - 32768, n = i >> 7, k = i & 127;
        g_wprojT[i] = __float2half(Wp[k * 128 + n]);
    } else if (idx < 49152 + 12544) {
        int i = idx - 49152;
        int h = i / 3136, r = (i % 3136) >> 6, c = i & 63;
        g_bias[i] = (c < 49) ? tbl[ridx[r * 49 + c] * 4 + h] : -1e9f;
    }
}

// ============================================================
// fused kernel — one CTA per window
// ============================================================
__global__ __launch_bounds__(256, 2)
void fused(const float* __restrict__ x, const float* __restrict__ q_global,
           const float* __restrict__ bkv, const float* __restrict__ bp,
           float* __restrict__ out)
{
    __half* As  = (__half*)dynsmem;      // [64][136]
    __half* Bs  = As + F_BS;             // [128][136]
    __half* kvs = As + F_KV;             // [64][264]
    __half* qs  = As + F_QS;             // [4][64][40]
    const int b = blockIdx.x, t = threadIdx.x, l = t & 31, wid = t >> 5;
    const uint32_t sbA = smem_u32(As), sbB = smem_u32(Bs), sbKV = smem_u32(kvs);
    const uint32_t sbQ = smem_u32(qs);
    const int l2 = 2 * (l & 3), l4 = l >> 2;
    const int wm = (wid >> 2) * 32, wn = (wid & 3) * 32;   // GEMM warp grid

    // ---------- phase 1: x -> fp16 As, q -> fp16 qs ----------
    {
        const float* xrow = x + (size_t)b * NWIN * DIMC;
        for (int i = t; i < 1568; i += 256) {              // 49 rows * 32 float4
            int row = i >> 5, f4 = i & 31;
            float4 v = *(const float4*)(xrow + row * DIMC + f4 * 4);
            *(uint2*)&As[row * 136 + f4 * 4] = make_uint2(
                h2u(__floats2half2_rn(v.x, v.y)), h2u(__floats2half2_rn(v.z, v.w)));
        }
        if (t < 240) {                                     // 15 pad rows * 16 uint4
            int row = 49 + (t >> 4), c = t & 15;
            *(uint4*)&As[row * 136 + c * 8] = make_uint4(0, 0, 0, 0);
        }
        const float* qg = q_global + (size_t)(b >> 6) * (HEADS * NWIN * 32);
        for (int i = t; i < 1568; i += 256) {              // 4*49*8 float4
            int h = i / 392, rem = i % 392, r = rem >> 3, f = rem & 7;
            float4 v = *(const float4*)(qg + (h * NWIN + r) * 32 + f * 4);
            *(uint2*)&qs[h * 2560 + r * 40 + f * 4] = make_uint2(
                h2u(__floats2half2_rn(v.x * SCALE, v.y * SCALE)),
                h2u(__floats2half2_rn(v.z * SCALE, v.w * SCALE)));
        }
        for (int i = t; i < 600; i += 256) {               // q pad rows
            int h = i / 150, rr = (i % 150) / 10, u = i % 10;
            *(uint2*)&qs[h * 2560 + (49 + rr) * 40 + u * 4] = make_uint2(0, 0);
        }
    }

    // ---------- phase 2: kv GEMM, two N=128 passes ----------
    #pragma unroll 1
    for (int pass = 0; pass < 2; pass++) {
        __syncthreads();                                   // As/qs ready | prev ldsm done
        const __half* wsrc = g_wkvT + pass * (128 * 128);
        #pragma unroll
        for (int p = 0; p < 8; p++) {
            int i = t + p * 256;
            int row = i >> 4, c = i & 15;
            *(uint4*)&Bs[row * 136 + c * 8] = *(const uint4*)&wsrc[row * 128 + c * 8];
        }
        __syncthreads();

        float acc[2][4][4];
        #pragma unroll
        for (int i = 0; i < 2; i++)
            #pragma unroll
            for (int j = 0; j < 4; j++)
                acc[i][j][0] = acc[i][j][1] = acc[i][j][2] = acc[i][j][3] = 0.f;
        gemm64x128(sbA, sbB, wm, wn, l, acc);

        // epilogue: +bias -> kvs[:, pass*128 + c]
        #pragma unroll
        for (int i = 0; i < 2; i++) {
            int rA = wm + 16 * i + l4;
            #pragma unroll
            for (int j = 0; j < 4; j++) {
                int c = wn + 8 * j + l2;
                float2 bb = *(const float2*)&bkv[pass * 128 + c];
                *(__half2*)&kvs[rA * 264 + pass * 128 + c] =
                    __floats2half2_rn(acc[i][j][0] + bb.x, acc[i][j][1] + bb.y);
                *(__half2*)&kvs[(rA + 8) * 264 + pass * 128 + c] =
                    __floats2half2_rn(acc[i][j][2] + bb.x, acc[i][j][3] + bb.y);
            }
        }
    }
    __syncthreads();                                       // kvs complete; Bs ldsm done

    // prefetch W_proj into Bs (overlaps attention compute)
    #pragma unroll
    for (int p = 0; p < 8; p++) {
        int i = t + p * 256;
        int row = i >> 4, c = i & 15;
        *(uint4*)&Bs[row * 136 + c * 8] = *(const uint4*)&g_wprojT[row * 128 + c * 8];
    }

    // ---------- phase 3: attention (fragment-resident) ----------
    {
        const int h = wid >> 1, am = (wid & 1) * 32;       // attn warp grid: 4 heads x 2
        const uint32_t qbase = sbQ + (uint32_t)h * 2560u * 2u;

        float S[2][8][4];
        #pragma unroll
        for (int i = 0; i < 2; i++)
            #pragma unroll
            for (int j = 0; j < 8; j++)
                S[i][j][0] = S[i][j][1] = S[i][j][2] = S[i][j][3] = 0.f;

        #pragma unroll
        for (int kk = 0; kk < 32; kk += 16) {
            uint32_t a[2][4], bk[4][4];
            #pragma unroll
            for (int i = 0; i < 2; i++) LDSM_X4(a[i], ldsm_addr(qbase, am + 16 * i, 40, kk, l));
            #pragma unroll
            for (int g = 0; g < 4; g++)
                LDSM_X4(bk[g], ldsm_addr(sbKV, 16 * g, 264, h * 32 + kk, l));
            #pragma unroll
            for (int i = 0; i < 2; i++)
                #pragma unroll
                for (int g = 0; g < 4; g++) {
                    mma16816(S[i][2 * g],     a[i], bk[g][0], bk[g][2]);
                    mma16816(S[i][2 * g + 1], a[i], bk[g][1], bk[g][3]);
                }
        }

        uint32_t ph[2][4][4];
        #pragma unroll
        for (int i = 0; i < 2; i++) {
            int rA = am + 16 * i + l4, rB = rA + 8;
            const float* bA = &g_bias[(h * 49 + (rA < 49 ? rA : 48)) * 64];
            const float* bB = &g_bias[(h * 49 + (rB < 49 ? rB : 48)) * 64];
            #pragma unroll
            for (int j = 0; j < 8; j++) {
                float2 fA = *(const float2*)&bA[8 * j + l2];
                float2 fB = *(const float2*)&bB[8 * j + l2];
                S[i][j][0] += fA.x; S[i][j][1] += fA.y;
                S[i][j][2] += fB.x; S[i][j][3] += fB.y;
            }
            float mA = -1e30f, mB = -1e30f;
            #pragma unroll
            for (int j = 0; j < 8; j++) {
                mA = fmaxf(mA, fmaxf(S[i][j][0], S[i][j][1]));
                mB = fmaxf(mB, fmaxf(S[i][j][2], S[i][j][3]));
            }
            mA = fmaxf(mA, __shfl_xor_sync(0xffffffffu, mA, 1));
            mA = fmaxf(mA, __shfl_xor_sync(0xffffffffu, mA, 2));
            mB = fmaxf(mB, __shfl_xor_sync(0xffffffffu, mB, 1));
            mB = fmaxf(mB, __shfl_xor_sync(0xffffffffu, mB, 2));
            float sA = 0.f, sB = 0.f;
            #pragma unroll
            for (int j = 0; j < 8; j++) {
                S[i][j][0] = __expf(S[i][j][0] - mA); sA += S[i][j][0];
                S[i][j][1] = __expf(S[i][j][1] - mA); sA += S[i][j][1];
                S[i][j][2] = __expf(S[i][j][2] - mB); sB += S[i][j][2];
                S[i][j][3] = __expf(S[i][j][3] - mB); sB += S[i][j][3];
            }
            sA += __shfl_xor_sync(0xffffffffu, sA, 1);
            sA += __shfl_xor_sync(0xffffffffu, sA, 2);
            sB += __shfl_xor_sync(0xffffffffu, sB, 1);
            sB += __shfl_xor_sync(0xffffffffu, sB, 2);
            float iA = 1.f / sA, iB = 1.f / sB;
            #pragma unroll
            for (int tp = 0; tp < 4; tp++) {
                ph[i][tp][0] = h2u(__floats2half2_rn(S[i][2 * tp][0] * iA, S[i][2 * tp][1] * iA));
                ph[i][tp][1] = h2u(__floats2half2_rn(S[i][2 * tp][2] * iB, S[i][2 * tp][3] * iB));
                ph[i][tp][2] = h2u(__floats2half2_rn(S[i][2 * tp + 1][0] * iA, S[i][2 * tp + 1][1] * iA));
                ph[i][tp][3] = h2u(__floats2half2_rn(S[i][2 * tp + 1][2] * iB, S[i][2 * tp + 1][3] * iB));
            }
        }

        float O[2][4][4];
        #pragma unroll
        for (int i = 0; i < 2; i++)
            #pragma unroll
            for (int j = 0; j < 4; j++)
                O[i][j][0] = O[i][j][1] = O[i][j][2] = O[i][j][3] = 0.f;

        #pragma unroll
        for (int tp = 0; tp < 4; tp++) {
            uint32_t bv[2][4];
            #pragma unroll
            for (int g = 0; g < 2; g++)
                LDSM_X4_T(bv[g], ldsm_addr(sbKV, 16 * tp, 264, 128 + h * 32 + 16 * g, l));
            #pragma unroll
            for (int i = 0; i < 2; i++)
                #pragma unroll
                for (int jd = 0; jd < 4; jd++) {
                    int g = jd >> 1;
                    if ((jd & 1) == 0) mma16816(O[i][jd], ph[i][tp], bv[g][0], bv[g][1]);
                    else               mma16816(O[i][jd], ph[i][tp], bv[g][2], bv[g][3]);
                }
        }

        // stage O into As (x tile is dead)  [64][136] halves
        #pragma unroll
        for (int i = 0; i < 2; i++) {
            int rA = am + 16 * i + l4;
            #pragma unroll
            for (int jd = 0; jd < 4; jd++) {
                int c = h * 32 + 8 * jd + l2;
                *(__half2*)&As[rA * 136 + c]       = __floats2half2_rn(O[i][jd][0], O[i][jd][1]);
                *(__half2*)&As[(rA + 8) * 136 + c] = __floats2half2_rn(O[i][jd][2], O[i][jd][3]);
            }
        }
    }
    __syncthreads();                                       // o staged + W_proj loaded + kvs free

    // ---------- phase 4: proj GEMM ----------
    {
        float acc[2][4][4];
        #pragma unroll
        for (int i = 0; i < 2; i++)
            #pragma unroll
            for (int j = 0; j < 4; j++)
                acc[i][j][0] = acc[i][j][1] = acc[i][j][2] = acc[i][j][3] = 0.f;
        gemm64x128(sbA, sbB, wm, wn, l, acc);

        // epilogue -> fp32 staging in kvs region [64][132]
        float* kvf = (float*)kvs;
        #pragma unroll
        for (int i = 0; i < 2; i++) {
            int rA = wm + 16 * i + l4;
            #pragma unroll
            for (int j = 0; j < 4; j++) {
                int c = wn + 8 * j + l2;
                float2 bb = *(const float2*)&bp[c];
                *(float2*)&kvf[rA * 132 + c]       = make_float2(acc[i][j][0] + bb.x, acc[i][j][1] + bb.y);
                *(float2*)&kvf[(rA + 8) * 132 + c] = make_float2(acc[i][j][2] + bb.x, acc[i][j][3] + bb.y);
            }
        }
        __syncthreads();
        float* dst = out + (size_t)b * NWIN * DIMC;
        for (int i = t; i < 1568; i += 256) {              // 49 rows * 32 float4
            int row = i >> 5, c4 = i & 31;
            *(float4*)&dst[row * DIMC + c4 * 4] = *(const float4*)&kvf[row * 132 + c4 * 4];
        }
    }
}

// ============================================================
extern "C" void kernel_launch(void* const* d_in, const int* in_sizes, int n_in,
                              void* d_out, int out_size)
{
    const float* x         = (const float*)d_in[0];
    const float* q_global  = (const float*)d_in[1];
    const float* tbl       = (const float*)d_in[2];
    const float* W_kv      = (const float*)d_in[3];
    const float* b_kv      = (const float*)d_in[4];
    const float* W_proj    = (const float*)d_in[5];
    const float* b_proj    = (const float*)d_in[6];
    const int*   rel_index = (const int*)d_in[7];
    float* out = (float*)d_out;

    cudaFuncSetAttribute(fused, cudaFuncAttributeMaxDynamicSharedMemorySize, FU_SMEM);

    prep <<<242, 256>>>(W_kv, W_proj, tbl, rel_index);
    fused<<<4096, 256, FU_SMEM>>>(x, q_global, b_kv, b_proj, out);
}

// round 14
// speedup vs baseline: 4.8692x; 1.2126x over previous
#include <cuda_runtime.h>
#include <cuda_fp16.h>
#include <cstdint>

// ============================================================
// WindowAttentionGlobal — fully fused, one CTA per window,
// 3 CTAs/SM (regs<=85 via launch_bounds, smem 69632B).
//   prep  : W_kv/W_proj -> fp16 transposed; bias table [4][49][64]
//   fused : x->fp16 -> kv GEMM (2 N-passes x 2 K-halves) ->
//           attention (per-warp sequential M-tiles, q direct from gmem) ->
//           proj GEMM (2 K-halves) -> out
// ============================================================

#define NWIN   49
#define DIMC   128
#define HEADS  4
#define SCALE  0.17677669529663689f

__device__ __half g_wkvT[256 * 128];     // [n][k]
__device__ __half g_wprojT[128 * 128];   // [n][k]
__device__ float  g_bias[4 * 49 * 64];   // [h][r][c], c>=49 -> -1e9

extern __shared__ char dynsmem[];

// smem layout (halves):
//   As  [64][136]  @0       17408 B  (x tile -> later o tile)
//   Bs  [128][72]  @8704    18432 B  (weight K-half chunk)
//   kvs [64][264]  @17920   33792 B  (kv tile; later fp32 out [64][132])
#define F_BS 8704
#define F_KV 17920
#define FU_SMEM ((8704 + 9216 + 16896) * 2)   // 69632 B

__device__ __forceinline__ uint32_t smem_u32(const void* p) {
    uint32_t a;
    asm("{ .reg .u64 t; cvta.to.shared.u64 t, %1; cvt.u32.u64 %0, t; }" : "=r"(a) : "l"(p));
    return a;
}
__device__ __forceinline__ uint32_t h2u(__half2 h) { return *reinterpret_cast<uint32_t*>(&h); }

#define LDSM_X4(r, addr)                                                      \
    asm volatile("ldmatrix.sync.aligned.m8n8.x4.shared.b16 {%0,%1,%2,%3}, [%4];" \
                 : "=r"((r)[0]), "=r"((r)[1]), "=r"((r)[2]), "=r"((r)[3]) : "r"(addr))
#define LDSM_X4_T(r, addr)                                                    \
    asm volatile("ldmatrix.sync.aligned.m8n8.x4.trans.shared.b16 {%0,%1,%2,%3}, [%4];" \
                 : "=r"((r)[0]), "=r"((r)[1]), "=r"((r)[2]), "=r"((r)[3]) : "r"(addr))

__device__ __forceinline__ void mma16816(float* d, const uint32_t* a,
                                         uint32_t b0, uint32_t b1) {
    asm volatile(
        "mma.sync.aligned.m16n8k16.row.col.f32.f16.f16.f32 "
        "{%0,%1,%2,%3}, {%4,%5,%6,%7}, {%8,%9}, {%0,%1,%2,%3};"
        : "+f"(d[0]), "+f"(d[1]), "+f"(d[2]), "+f"(d[3])
        : "r"(a[0]), "r"(a[1]), "r"(a[2]), "r"(a[3]), "r"(b0), "r"(b1));
}

__device__ __forceinline__ uint32_t ldsm_addr(uint32_t base2B, int row0, int pitch,
                                              int col0, int l) {
    int row = row0 + (l & 7) + ((l >> 3) & 1) * 8;
    int col = col0 + (l >> 4) * 8;
    return base2B + (uint32_t)(row * pitch + col) * 2u;
}

// 64x128 GEMM over one K=64 half: A[64][136] (cols k0base..), B[128][72]
__device__ __forceinline__ void gemm_k64(uint32_t sbA, uint32_t sbB, int k0base,
                                         int wm, int wn, int l, float acc[2][4][4]) {
    #pragma unroll
    for (int kk = 0; kk < 64; kk += 16) {
        uint32_t a[2][4], b[2][4];
        #pragma unroll
        for (int i = 0; i < 2; i++)
            LDSM_X4(a[i], ldsm_addr(sbA, wm + 16 * i, 136, k0base + kk, l));
        #pragma unroll
        for (int g = 0; g < 2; g++)
            LDSM_X4(b[g], ldsm_addr(sbB, wn + 16 * g, 72, kk, l));
        #pragma unroll
        for (int i = 0; i < 2; i++)
            #pragma unroll
            for (int g = 0; g < 2; g++) {
                mma16816(acc[i][2 * g],     a[i], b[g][0], b[g][2]);
                mma16816(acc[i][2 * g + 1], a[i], b[g][1], b[g][3]);
            }
    }
}

// ============================================================
__global__ void prep(const float* __restrict__ Wkv, const float* __restrict__ Wp,
                     const float* __restrict__ tbl, const int* __restrict__ ridx)
{
    int idx = blockIdx.x * 256 + threadIdx.x;
    if (idx < 32768) {
        int n = idx >> 7, k = idx & 127;
        g_wkvT[idx] = __float2half(Wkv[k * 256 + n]);
    } else if (idx < 49152) {
        int i = idx - 32768, n = i >> 7, k = i & 127;
        g_wprojT[i] = __float2half(Wp[k * 128 + n]);
    } else if (idx < 49152 + 12544) {
        int i = idx - 49152;
        int h = i / 3136, r = (i % 3136) >> 6, c = i & 63;
        g_bias[i] = (c < 49) ? tbl[ridx[r * 49 + c] * 4 + h] : -1e9f;
    }
}

// ============================================================
__global__ __launch_bounds__(256, 3)
void fused(const float* __restrict__ x, const float* __restrict__ q_global,
           const float* __restrict__ bkv, const float* __restrict__ bp,
           float* __restrict__ out)
{
    __half* As  = (__half*)dynsmem;      // [64][136]
    __half* Bs  = As + F_BS;             // [128][72]
    __half* kvs = As + F_KV;             // [64][264]
    const int b = blockIdx.x, t = threadIdx.x, l = t & 31, wid = t >> 5;
    const uint32_t sbA = smem_u32(As), sbB = smem_u32(Bs), sbKV = smem_u32(kvs);
    const int l2 = 2 * (l & 3), l4 = l >> 2;
    const int wm = (wid >> 2) * 32, wn = (wid & 3) * 32;   // GEMM warp grid 2Mx4N

    // ---------- phase 1: x -> fp16 As ----------
    {
        const float* xrow = x + (size_t)b * NWIN * DIMC;
        for (int i = t; i < 1568; i += 256) {              // 49 rows * 32 float4
            int row = i >> 5, f4 = i & 31;
            float4 v = *(const float4*)(xrow + row * DIMC + f4 * 4);
            *(uint2*)&As[row * 136 + f4 * 4] = make_uint2(
                h2u(__floats2half2_rn(v.x, v.y)), h2u(__floats2half2_rn(v.z, v.w)));
        }
        if (t < 240) {                                     // 15 pad rows * 16 uint4
            int row = 49 + (t >> 4), c = t & 15;
            *(uint4*)&As[row * 136 + c * 8] = make_uint4(0, 0, 0, 0);
        }
    }

    // ---------- phase 2: kv GEMM (2 N-passes x 2 K-halves) ----------
    #pragma unroll 1
    for (int pass = 0; pass < 2; pass++) {
        float acc[2][4][4];
        #pragma unroll
        for (int i = 0; i < 2; i++)
            #pragma unroll
            for (int j = 0; j < 4; j++)
                acc[i][j][0] = acc[i][j][1] = acc[i][j][2] = acc[i][j][3] = 0.f;

        #pragma unroll 1
        for (int ks = 0; ks < 2; ks++) {
            __syncthreads();                               // prev Bs consumers done
            const __half* wsrc = g_wkvT + (size_t)(pass * 128) * 128 + ks * 64;
            #pragma unroll
            for (int p = 0; p < 4; p++) {                  // 1024 uint4
                int i = t + p * 256;
                int row = i >> 3, c = i & 7;
                *(uint4*)&Bs[row * 72 + c * 8] = *(const uint4*)&wsrc[row * 128 + c * 8];
            }
            __syncthreads();
            gemm_k64(sbA, sbB, ks * 64, wm, wn, l, acc);
        }
        // epilogue: +bias -> kvs[:, pass*128 + c]
        #pragma unroll
        for (int i = 0; i < 2; i++) {
            int rA = wm + 16 * i + l4;
            #pragma unroll
            for (int j = 0; j < 4; j++) {
                int c = wn + 8 * j + l2;
                float2 bb = *(const float2*)&bkv[pass * 128 + c];
                *(__half2*)&kvs[rA * 264 + pass * 128 + c] =
                    __floats2half2_rn(acc[i][j][0] + bb.x, acc[i][j][1] + bb.y);
                *(__half2*)&kvs[(rA + 8) * 264 + pass * 128 + c] =
                    __floats2half2_rn(acc[i][j][2] + bb.x, acc[i][j][3] + bb.y);
            }
        }
    }
    __syncthreads();                                       // kvs complete, Bs free

    // prefetch W_proj K-half 0 into Bs (overlaps attention)
    #pragma unroll
    for (int p = 0; p < 4; p++) {
        int i = t + p * 256;
        int row = i >> 3, c = i & 7;
        *(uint4*)&Bs[row * 72 + c * 8] = *(const uint4*)&g_wprojT[(size_t)row * 128 + c * 8];
    }

    // ---------- phase 3: attention (per-warp sequential M-tiles) ----------
    {
        const int h = wid >> 1, am = (wid & 1) * 32;       // 4 heads x 2 row-halves
        const float* qg = q_global + ((size_t)(b >> 6) * HEADS + h) * (NWIN * 32);

        #pragma unroll 1
        for (int i = 0; i < 2; i++) {
            const int rA = am + 16 * i + l4, rB = rA + 8;
            const int q0 = (rA < 49) ? rA : 48, q1 = (rB < 49) ? rB : 48;

            // Q A-fragments direct from gmem (scaled)
            uint32_t aq[2][4];
            #pragma unroll
            for (int kh = 0; kh < 2; kh++) {
                int c = kh * 16 + l2;
                float2 v00 = *(const float2*)&qg[q0 * 32 + c];
                float2 v10 = *(const float2*)&qg[q1 * 32 + c];
                float2 v01 = *(const float2*)&qg[q0 * 32 + c + 8];
                float2 v11 = *(const float2*)&qg[q1 * 32 + c + 8];
                aq[kh][0] = h2u(__floats2half2_rn(v00.x * SCALE, v00.y * SCALE));
                aq[kh][1] = h2u(__floats2half2_rn(v10.x * SCALE, v10.y * SCALE));
                aq[kh][2] = h2u(__floats2half2_rn(v01.x * SCALE, v01.y * SCALE));
                aq[kh][3] = h2u(__floats2half2_rn(v11.x * SCALE, v11.y * SCALE));
            }

            // QK^T: S[16 rows][64 keys]
            float S[8][4];
            #pragma unroll
            for (int j = 0; j < 8; j++)
                S[j][0] = S[j][1] = S[j][2] = S[j][3] = 0.f;
            #pragma unroll
            for (int kh = 0; kh < 2; kh++) {
                uint32_t bk[4][4];
                #pragma unroll
                for (int g = 0; g < 4; g++)
                    LDSM_X4(bk[g], ldsm_addr(sbKV, 16 * g, 264, h * 32 + kh * 16, l));
                #pragma unroll
                for (int g = 0; g < 4; g++) {
                    mma16816(S[2 * g],     aq[kh], bk[g][0], bk[g][2]);
                    mma16816(S[2 * g + 1], aq[kh], bk[g][1], bk[g][3]);
                }
            }

            // bias + softmax
            const float* bA = &g_bias[(h * 49 + q0) * 64];
            const float* bB = &g_bias[(h * 49 + q1) * 64];
            #pragma unroll
            for (int j = 0; j < 8; j++) {
                float2 fA = *(const float2*)&bA[8 * j + l2];
                float2 fB = *(const float2*)&bB[8 * j + l2];
                S[j][0] += fA.x; S[j][1] += fA.y;
                S[j][2] += fB.x; S[j][3] += fB.y;
            }
            float mA = -1e30f, mB = -1e30f;
            #pragma unroll
            for (int j = 0; j < 8; j++) {
                mA = fmaxf(mA, fmaxf(S[j][0], S[j][1]));
                mB = fmaxf(mB, fmaxf(S[j][2], S[j][3]));
            }
            mA = fmaxf(mA, __shfl_xor_sync(0xffffffffu, mA, 1));
            mA = fmaxf(mA, __shfl_xor_sync(0xffffffffu, mA, 2));
            mB = fmaxf(mB, __shfl_xor_sync(0xffffffffu, mB, 1));
            mB = fmaxf(mB, __shfl_xor_sync(0xffffffffu, mB, 2));
            float sA = 0.f, sB = 0.f;
            #pragma unroll
            for (int j = 0; j < 8; j++) {
                S[j][0] = __expf(S[j][0] - mA); sA += S[j][0];
                S[j][1] = __expf(S[j][1] - mA); sA += S[j][1];
                S[j][2] = __expf(S[j][2] - mB); sB += S[j][2];
                S[j][3] = __expf(S[j][3] - mB); sB += S[j][3];
            }
            sA += __shfl_xor_sync(0xffffffffu, sA, 1);
            sA += __shfl_xor_sync(0xffffffffu, sA, 2);
            sB += __shfl_xor_sync(0xffffffffu, sB, 1);
            sB += __shfl_xor_sync(0xffffffffu, sB, 2);
            const float iA = 1.f / sA, iB = 1.f / sB;

            uint32_t ph[4][4];
            #pragma unroll
            for (int tp = 0; tp < 4; tp++) {
                ph[tp][0] = h2u(__floats2half2_rn(S[2 * tp][0] * iA, S[2 * tp][1] * iA));
                ph[tp][1] = h2u(__floats2half2_rn(S[2 * tp][2] * iB, S[2 * tp][3] * iB));
                ph[tp][2] = h2u(__floats2half2_rn(S[2 * tp + 1][0] * iA, S[2 * tp + 1][1] * iA));
                ph[tp][3] = h2u(__floats2half2_rn(S[2 * tp + 1][2] * iB, S[2 * tp + 1][3] * iB));
            }

            // PV: O[16 rows][32 dims]
            float O[4][4];
            #pragma unroll
            for (int j = 0; j < 4; j++)
                O[j][0] = O[j][1] = O[j][2] = O[j][3] = 0.f;
            #pragma unroll
            for (int tp = 0; tp < 4; tp++) {
                uint32_t bv[2][4];
                #pragma unroll
                for (int g = 0; g < 2; g++)
                    LDSM_X4_T(bv[g], ldsm_addr(sbKV, 16 * tp, 264, 128 + h * 32 + 16 * g, l));
                #pragma unroll
                for (int jd = 0; jd < 4; jd++) {
                    int g = jd >> 1;
                    if ((jd & 1) == 0) mma16816(O[jd], ph[tp], bv[g][0], bv[g][1]);
                    else               mma16816(O[jd], ph[tp], bv[g][2], bv[g][3]);
                }
            }

            // stage O into As (x tile dead)
            #pragma unroll
            for (int jd = 0; jd < 4; jd++) {
                int c = h * 32 + 8 * jd + l2;
                *(__half2*)&As[rA * 136 + c] = __floats2half2_rn(O[jd][0], O[jd][1]);
                *(__half2*)&As[rB * 136 + c] = __floats2half2_rn(O[jd][2], O[jd][3]);
            }
        }
    }
    __syncthreads();                                       // O staged + W_proj ks0 loaded

    // ---------- phase 4: proj GEMM (2 K-halves) ----------
    {
        float acc[2][4][4];
        #pragma unroll
        for (int i = 0; i < 2; i++)
            #pragma unroll
            for (int j = 0; j < 4; j++)
                acc[i][j][0] = acc[i][j][1] = acc[i][j][2] = acc[i][j][3] = 0.f;

        gemm_k64(sbA, sbB, 0, wm, wn, l, acc);
        __syncthreads();                                   // ldsm done -> reload Bs
        #pragma unroll
        for (int p = 0; p < 4; p++) {
            int i = t + p * 256;
            int row = i >> 3, c = i & 7;
            *(uint4*)&Bs[row * 72 + c * 8] = *(const uint4*)&g_wprojT[(size_t)row * 128 + 64 + c * 8];
        }
        __syncthreads();
        gemm_k64(sbA, sbB, 64, wm, wn, l, acc);

        // epilogue -> fp32 staging in kvs region [64][132]
        __syncthreads();                                   // kvs ldsm (PV) long done; keep order
        float* kvf = (float*)kvs;
        #pragma unroll
        for (int i = 0; i < 2; i++) {
            int rA = wm + 16 * i + l4;
            #pragma unroll
            for (int j = 0; j < 4; j++) {
                int c = wn + 8 * j + l2;
                float2 bb = *(const float2*)&bp[c];
                *(float2*)&kvf[rA * 132 + c]       = make_float2(acc[i][j][0] + bb.x, acc[i][j][1] + bb.y);
                *(float2*)&kvf[(rA + 8) * 132 + c] = make_float2(acc[i][j][2] + bb.x, acc[i][j][3] + bb.y);
            }
        }
        __syncthreads();
        float* dst = out + (size_t)b * NWIN * DIMC;
        for (int i = t; i < 1568; i += 256) {              // 49 rows * 32 float4
            int row = i >> 5, c4 = i & 31;
            *(float4*)&dst[row * DIMC + c4 * 4] = *(const float4*)&kvf[row * 132 + c4 * 4];
        }
    }
}

// ============================================================
extern "C" void kernel_launch(void* const* d_in, const int* in_sizes, int n_in,
                              void* d_out, int out_size)
{
    const float* x         = (const float*)d_in[0];
    const float* q_global  = (const float*)d_in[1];
    const float* tbl       = (const float*)d_in[2];
    const float* W_kv      = (const float*)d_in[3];
    const float* b_kv      = (const float*)d_in[4];
    const float* W_proj    = (const float*)d_in[5];
    const float* b_proj    = (const float*)d_in[6];
    const int*   rel_index = (const int*)d_in[7];
    float* out = (float*)d_out;

    cudaFuncSetAttribute(fused, cudaFuncAttributeMaxDynamicSharedMemorySize, FU_SMEM);

    prep <<<242, 256>>>(W_kv, W_proj, tbl, rel_index);
    fused<<<4096, 256, FU_SMEM>>>(x, q_global, b_kv, b_proj, out);
}

// round 16
// speedup vs baseline: 4.9757x; 1.0219x over previous
#include <cuda_runtime.h>
#include <cuda_fp16.h>
#include <cstdint>

// ============================================================
// WindowAttentionGlobal — fully fused, one CTA per window,
// 3 CTAs/SM (regs<=85 via launch_bounds, smem 69632B).
// Weight staging via cp.async (halves L1 wavefronts on that path).
//   prep  : W_kv/W_proj -> fp16 transposed; bias table [4][49][64]
//   fused : x->fp16 -> kv GEMM (2 N-passes x 2 K-halves) ->
//           attention (per-warp sequential M-tiles, q direct from gmem,
//                      W_proj half-0 cp.async'd underneath) ->
//           proj GEMM (2 K-halves) -> out
// ============================================================

#define NWIN   49
#define DIMC   128
#define HEADS  4
#define SCALE  0.17677669529663689f

__device__ __half g_wkvT[256 * 128];     // [n][k]
__device__ __half g_wprojT[128 * 128];   // [n][k]
__device__ float  g_bias[4 * 49 * 64];   // [h][r][c], c>=49 -> -1e9

extern __shared__ char dynsmem[];

// smem layout (halves):
//   As  [64][136]  @0       17408 B  (x tile -> later o tile)
//   Bs  [128][72]  @8704    18432 B  (weight K-half chunk)
//   kvs [64][264]  @17920   33792 B  (kv tile; later fp32 out [64][132])
#define F_BS 8704
#define F_KV 17920
#define FU_SMEM ((8704 + 9216 + 16896) * 2)   // 69632 B

__device__ __forceinline__ uint32_t smem_u32(const void* p) {
    uint32_t a;
    asm("{ .reg .u64 t; cvta.to.shared.u64 t, %1; cvt.u32.u64 %0, t; }" : "=r"(a) : "l"(p));
    return a;
}
__device__ __forceinline__ uint32_t h2u(__half2 h) { return *reinterpret_cast<uint32_t*>(&h); }

#define LDSM_X4(r, addr)                                                      \
    asm volatile("ldmatrix.sync.aligned.m8n8.x4.shared.b16 {%0,%1,%2,%3}, [%4];" \
                 : "=r"((r)[0]), "=r"((r)[1]), "=r"((r)[2]), "=r"((r)[3]) : "r"(addr))
#define LDSM_X4_T(r, addr)                                                    \
    asm volatile("ldmatrix.sync.aligned.m8n8.x4.trans.shared.b16 {%0,%1,%2,%3}, [%4];" \
                 : "=r"((r)[0]), "=r"((r)[1]), "=r"((r)[2]), "=r"((r)[3]) : "r"(addr))

__device__ __forceinline__ void mma16816(float* d, const uint32_t* a,
                                         uint32_t b0, uint32_t b1) {
    asm volatile(
        "mma.sync.aligned.m16n8k16.row.col.f32.f16.f16.f32 "
        "{%0,%1,%2,%3}, {%4,%5,%6,%7}, {%8,%9}, {%0,%1,%2,%3};"
        : "+f"(d[0]), "+f"(d[1]), "+f"(d[2]), "+f"(d[3])
        : "r"(a[0]), "r"(a[1]), "r"(a[2]), "r"(a[3]), "r"(b0), "r"(b1));
}

__device__ __forceinline__ void cp16(uint32_t saddr, const void* g) {
    asm volatile("cp.async.cg.shared.global [%0], [%1], 16;" :: "r"(saddr), "l"(g));
}
#define CP_COMMIT() asm volatile("cp.async.commit_group;" ::: "memory")
#define CP_WAIT0()  asm volatile("cp.async.wait_group 0;" ::: "memory")

__device__ __forceinline__ uint32_t ldsm_addr(uint32_t base2B, int row0, int pitch,
                                              int col0, int l) {
    int row = row0 + (l & 7) + ((l >> 3) & 1) * 8;
    int col = col0 + (l >> 4) * 8;
    return base2B + (uint32_t)(row * pitch + col) * 2u;
}

// stage one [128 n-rows][64 k-halves] weight chunk into Bs via cp.async
__device__ __forceinline__ void stage_w(uint32_t sbB, const __half* wsrc, int t) {
    #pragma unroll
    for (int p = 0; p < 4; p++) {                  // 1024 x 16B
        int i = t + p * 256;
        int row = i >> 3, c = i & 7;
        cp16(sbB + (uint32_t)(row * 72 + c * 8) * 2u, wsrc + row * 128 + c * 8);
    }
    CP_COMMIT();
}

// 64x128 GEMM over one K=64 half: A[64][136] (cols k0base..), B[128][72]
__device__ __forceinline__ void gemm_k64(uint32_t sbA, uint32_t sbB, int k0base,
                                         int wm, int wn, int l, float acc[2][4][4]) {
    #pragma unroll
    for (int kk = 0; kk < 64; kk += 16) {
        uint32_t a[2][4], b[2][4];
        #pragma unroll
        for (int i = 0; i < 2; i++)
            LDSM_X4(a[i], ldsm_addr(sbA, wm + 16 * i, 136, k0base + kk, l));
        #pragma unroll
        for (int g = 0; g < 2; g++)
            LDSM_X4(b[g], ldsm_addr(sbB, wn + 16 * g, 72, kk, l));
        #pragma unroll
        for (int i = 0; i < 2; i++)
            #pragma unroll
            for (int g = 0; g < 2; g++) {
                mma16816(acc[i][2 * g],     a[i], b[g][0], b[g][2]);
                mma16816(acc[i][2 * g + 1], a[i], b[g][1], b[g][3]);
            }
    }
}

// ============================================================
__global__ void prep(const float* __restrict__ Wkv, const float* __restrict__ Wp,
                     const float* __restrict__ tbl, const int* __restrict__ ridx)
{
    int idx = blockIdx.x * 256 + threadIdx.x;
    if (idx < 32768) {
        int n = idx >> 7, k = idx & 127;
        g_wkvT[idx] = __float2half(Wkv[k * 256 + n]);
    } else if (idx < 49152) {
        int i = idx - 32768, n = i >> 7, k = i & 127;
        g_wprojT[i] = __float2half(Wp[k * 128 + n]);
    } else if (idx < 49152 + 12544) {
        int i = idx - 49152;
        int h = i / 3136, r = (i % 3136) >> 6, c = i & 63;
        g_bias[i] = (c < 49) ? tbl[ridx[r * 49 + c] * 4 + h] : -1e9f;
    }
}

// ============================================================
__global__ __launch_bounds__(256, 3)
void fused(const float* __restrict__ x, const float* __restrict__ q_global,
           const float* __restrict__ bkv, const float* __restrict__ bp,
           float* __restrict__ out)
{
    __half* As  = (__half*)dynsmem;      // [64][136]
    __half* Bs  = As + F_BS;             // [128][72]
    __half* kvs = As + F_KV;             // [64][264]
    const int b = blockIdx.x, t = threadIdx.x, l = t & 31, wid = t >> 5;
    const uint32_t sbA = smem_u32(As), sbB = smem_u32(Bs), sbKV = smem_u32(kvs);
    const int l2 = 2 * (l & 3), l4 = l >> 2;
    const int wm = (wid >> 2) * 32, wn = (wid & 3) * 32;   // GEMM warp grid 2Mx4N

    // issue first weight chunk immediately (rides under x load)
    stage_w(sbB, g_wkvT, t);

    // ---------- phase 1: x -> fp16 As ----------
    {
        const float* xrow = x + (size_t)b * NWIN * DIMC;
        for (int i = t; i < 1568; i += 256) {              // 49 rows * 32 float4
            int row = i >> 5, f4 = i & 31;
            float4 v = *(const float4*)(xrow + row * DIMC + f4 * 4);
            *(uint2*)&As[row * 136 + f4 * 4] = make_uint2(
                h2u(__floats2half2_rn(v.x, v.y)), h2u(__floats2half2_rn(v.z, v.w)));
        }
        if (t < 240) {                                     // 15 pad rows * 16 uint4
            int row = 49 + (t >> 4), c = t & 15;
            *(uint4*)&As[row * 136 + c * 8] = make_uint4(0, 0, 0, 0);
        }
    }

    // ---------- phase 2: kv GEMM (2 N-passes x 2 K-halves) ----------
    #pragma unroll 1
    for (int pass = 0; pass < 2; pass++) {
        float acc[2][4][4];
        #pragma unroll
        for (int i = 0; i < 2; i++)
            #pragma unroll
            for (int j = 0; j < 4; j++)
                acc[i][j][0] = acc[i][j][1] = acc[i][j][2] = acc[i][j][3] = 0.f;

        #pragma unroll 1
        for (int ks = 0; ks < 2; ks++) {
            // chunk for (pass, ks) was issued at end of previous iteration
            // (or before phase 1 for the very first)
            CP_WAIT0();
            __syncthreads();                               // chunk visible to all
            gemm_k64(sbA, sbB, ks * 64, wm, wn, l, acc);
            __syncthreads();                               // all ldsm of Bs done
            // issue next chunk: (pass,ks+1) -> (pass+1,0) -> none (W_proj issued later)
            int nxt = pass * 2 + ks + 1;
            if (nxt < 4)
                stage_w(sbB, g_wkvT + (size_t)((nxt >> 1) * 128) * 128 + (nxt & 1) * 64, t);
        }
        // epilogue: +bias -> kvs[:, pass*128 + c]
        #pragma unroll
        for (int i = 0; i < 2; i++) {
            int rA = wm + 16 * i + l4;
            #pragma unroll
            for (int j = 0; j < 4; j++) {
                int c = wn + 8 * j + l2;
                float2 bb = *(const float2*)&bkv[pass * 128 + c];
                *(__half2*)&kvs[rA * 264 + pass * 128 + c] =
                    __floats2half2_rn(acc[i][j][0] + bb.x, acc[i][j][1] + bb.y);
                *(__half2*)&kvs[(rA + 8) * 264 + pass * 128 + c] =
                    __floats2half2_rn(acc[i][j][2] + bb.x, acc[i][j][3] + bb.y);
            }
        }
    }
    // issue W_proj K-half 0 (overlaps entire attention phase)
    stage_w(sbB, g_wprojT, t);
    __syncthreads();                                       // kvs complete everywhere

    // ---------- phase 3: attention (per-warp sequential M-tiles) ----------
    {
        const int h = wid >> 1, am = (wid & 1) * 32;       // 4 heads x 2 row-halves
        const float* qg = q_global + ((size_t)(b >> 6) * HEADS + h) * (NWIN * 32);

        #pragma unroll 1
        for (int i = 0; i < 2; i++) {
            const int rA = am + 16 * i + l4, rB = rA + 8;
            const int q0 = (rA < 49) ? rA : 48, q1 = (rB < 49) ? rB : 48;

            // Q A-fragments direct from gmem (scaled)
            uint32_t aq[2][4];
            #pragma unroll
            for (int kh = 0; kh < 2; kh++) {
                int c = kh * 16 + l2;
                float2 v00 = *(const float2*)&qg[q0 * 32 + c];
                float2 v10 = *(const float2*)&qg[q1 * 32 + c];
                float2 v01 = *(const float2*)&qg[q0 * 32 + c + 8];
                float2 v11 = *(const float2*)&qg[q1 * 32 + c + 8];
                aq[kh][0] = h2u(__floats2half2_rn(v00.x * SCALE, v00.y * SCALE));
                aq[kh][1] = h2u(__floats2half2_rn(v10.x * SCALE, v10.y * SCALE));
                aq[kh][2] = h2u(__floats2half2_rn(v01.x * SCALE, v01.y * SCALE));
                aq[kh][3] = h2u(__floats2half2_rn(v11.x * SCALE, v11.y * SCALE));
            }

            // QK^T: S[16 rows][64 keys]
            float S[8][4];
            #pragma unroll
            for (int j = 0; j < 8; j++)
                S[j][0] = S[j][1] = S[j][2] = S[j][3] = 0.f;
            #pragma unroll
            for (int kh = 0; kh < 2; kh++) {
                uint32_t bk[4][4];
                #pragma unroll
                for (int g = 0; g < 4; g++)
                    LDSM_X4(bk[g], ldsm_addr(sbKV, 16 * g, 264, h * 32 + kh * 16, l));
                #pragma unroll
                for (int g = 0; g < 4; g++) {
                    mma16816(S[2 * g],     aq[kh], bk[g][0], bk[g][2]);
                    mma16816(S[2 * g + 1], aq[kh], bk[g][1], bk[g][3]);
                }
            }

            // bias + softmax
            const float* bA = &g_bias[(h * 49 + q0) * 64];
            const float* bB = &g_bias[(h * 49 + q1) * 64];
            #pragma unroll
            for (int j = 0; j < 8; j++) {
                float2 fA = *(const float2*)&bA[8 * j + l2];
                float2 fB = *(const float2*)&bB[8 * j + l2];
                S[j][0] += fA.x; S[j][1] += fA.y;
                S[j][2] += fB.x; S[j][3] += fB.y;
            }
            float mA = -1e30f, mB = -1e30f;
            #pragma unroll
            for (int j = 0; j < 8; j++) {
                mA = fmaxf(mA, fmaxf(S[j][0], S[j][1]));
                mB = fmaxf(mB, fmaxf(S[j][2], S[j][3]));
            }
            mA = fmaxf(mA, __shfl_xor_sync(0xffffffffu, mA, 1));
            mA = fmaxf(mA, __shfl_xor_sync(0xffffffffu, mA, 2));
            mB = fmaxf(mB, __shfl_xor_sync(0xffffffffu, mB, 1));
            mB = fmaxf(mB, __shfl_xor_sync(0xffffffffu, mB, 2));
            float sA = 0.f, sB = 0.f;
            #pragma unroll
            for (int j = 0; j < 8; j++) {
                S[j][0] = __expf(S[j][0] - mA); sA += S[j][0];
                S[j][1] = __expf(S[j][1] - mA); sA += S[j][1];
                S[j][2] = __expf(S[j][2] - mB); sB += S[j][2];
                S[j][3] = __expf(S[j][3] - mB); sB += S[j][3];
            }
            sA += __shfl_xor_sync(0xffffffffu, sA, 1);
            sA += __shfl_xor_sync(0xffffffffu, sA, 2);
            sB += __shfl_xor_sync(0xffffffffu, sB, 1);
            sB += __shfl_xor_sync(0xffffffffu, sB, 2);
            const float iA = 1.f / sA, iB = 1.f / sB;

            uint32_t ph[4][4];
            #pragma unroll
            for (int tp = 0; tp < 4; tp++) {
                ph[tp][0] = h2u(__floats2half2_rn(S[2 * tp][0] * iA, S[2 * tp][1] * iA));
                ph[tp][1] = h2u(__floats2half2_rn(S[2 * tp][2] * iB, S[2 * tp][3] * iB));
                ph[tp][2] = h2u(__floats2half2_rn(S[2 * tp + 1][0] * iA, S[2 * tp + 1][1] * iA));
                ph[tp][3] = h2u(__floats2half2_rn(S[2 * tp + 1][2] * iB, S[2 * tp + 1][3] * iB));
            }

            // PV: O[16 rows][32 dims]
            float O[4][4];
            #pragma unroll
            for (int j = 0; j < 4; j++)
                O[j][0] = O[j][1] = O[j][2] = O[j][3] = 0.f;
            #pragma unroll
            for (int tp = 0; tp < 4; tp++) {
                uint32_t bv[2][4];
                #pragma unroll
                for (int g = 0; g < 2; g++)
                    LDSM_X4_T(bv[g], ldsm_addr(sbKV, 16 * tp, 264, 128 + h * 32 + 16 * g, l));
                #pragma unroll
                for (int jd = 0; jd < 4; jd++) {
                    int g = jd >> 1;
                    if ((jd & 1) == 0) mma16816(O[jd], ph[tp], bv[g][0], bv[g][1]);
                    else               mma16816(O[jd], ph[tp], bv[g][2], bv[g][3]);
                }
            }

            // stage O into As (x tile dead)
            #pragma unroll
            for (int jd = 0; jd < 4; jd++) {
                int c = h * 32 + 8 * jd + l2;
                *(__half2*)&As[rA * 136 + c] = __floats2half2_rn(O[jd][0], O[jd][1]);
                *(__half2*)&As[rB * 136 + c] = __floats2half2_rn(O[jd][2], O[jd][3]);
            }
        }
    }
    CP_WAIT0();                                            // own W_proj ks0 copies done
    __syncthreads();                                       // O staged + all copies visible

    // ---------- phase 4: proj GEMM (2 K-halves) ----------
    {
        float acc[2][4][4];
        #pragma unroll
        for (int i = 0; i < 2; i++)
            #pragma unroll
            for (int j = 0; j < 4; j++)
                acc[i][j][0] = acc[i][j][1] = acc[i][j][2] = acc[i][j][3] = 0.f;

        gemm_k64(sbA, sbB, 0, wm, wn, l, acc);
        __syncthreads();                                   // Bs ldsm done -> reload
        stage_w(sbB, g_wprojT + 64, t);
        CP_WAIT0();
        __syncthreads();
        gemm_k64(sbA, sbB, 64, wm, wn, l, acc);

        // epilogue -> fp32 staging in kvs region [64][132]
        __syncthreads();                                   // kvs (PV ldsm) reuse safe
        float* kvf = (float*)kvs;
        #pragma unroll
        for (int i = 0; i < 2; i++) {
            int rA = wm + 16 * i + l4;
            #pragma unroll
            for (int j = 0; j < 4; j++) {
                int c = wn + 8 * j + l2;
                float2 bb = *(const float2*)&bp[c];
                *(float2*)&kvf[rA * 132 + c]       = make_float2(acc[i][j][0] + bb.x, acc[i][j][1] + bb.y);
                *(float2*)&kvf[(rA + 8) * 132 + c] = make_float2(acc[i][j][2] + bb.x, acc[i][j][3] + bb.y);
            }
        }
        __syncthreads();
        float* dst = out + (size_t)b * NWIN * DIMC;
        for (int i = t; i < 1568; i += 256) {              // 49 rows * 32 float4
            int row = i >> 5, c4 = i & 31;
            *(float4*)&dst[row * DIMC + c4 * 4] = *(const float4*)&kvf[row * 132 + c4 * 4];
        }
    }
}

// ============================================================
extern "C" void kernel_launch(void* const* d_in, const int* in_sizes, int n_in,
                              void* d_out, int out_size)
{
    const float* x         = (const float*)d_in[0];
    const float* q_global  = (const float*)d_in[1];
    const float* tbl       = (const float*)d_in[2];
    const float* W_kv      = (const float*)d_in[3];
    const float* b_kv      = (const float*)d_in[4];
    const float* W_proj    = (const float*)d_in[5];
    const float* b_proj    = (const float*)d_in[6];
    const int*   rel_index = (const int*)d_in[7];
    float* out = (float*)d_out;

    cudaFuncSetAttribute(fused, cudaFuncAttributeMaxDynamicSharedMemorySize, FU_SMEM);

    prep <<<242, 256>>>(W_kv, W_proj, tbl, rel_index);
    fused<<<4096, 256, FU_SMEM>>>(x, q_global, b_kv, b_proj, out);
}